// round 11
// baseline (speedup 1.0000x reference)
#include <cuda_runtime.h>
#include <cuda_fp16.h>
#include <stdint.h>
#include <math.h>

#define D_IN     32
#define KF       832            // padded feature dim (26*32)
#define DIM      512
#define D_OUT    10
#define NX       1024
#define NC       100000
#define NCPAD    102400         // 400 * 256
#define NROWS    (NCPAD + NX)   // 103424 = 808*128
#define NSPLIT2  1600           // 400 cand-blocks x 4 n-warps
#define TWO_PI   6.283185307179586f

// stage geometry: K-chunk 32 halves (64B) per tile row, 80B padded stride
// A tile 128 rows, B tile 256 rows
#define ROWSTR   80
#define TILEA    (128 * ROWSTR)     // 10240
#define TILEBB   (256 * ROWSTR)     // 20480
#define STAGEB   (TILEA + TILEBB)   // 30720
#define NSTAGE   3
#define DYNSMEM  (NSTAGE * STAGEB)  // 92160

// ---------------- device scratch (alloc-free) ----------------
__device__ __align__(16) __half g_fb[(size_t)NROWS * KF];   // fp16 feats
__device__ __align__(16) __half g_wb[(size_t)DIM * KF];     // fp16 enc_w
__device__ __align__(16) __half g_emb[(size_t)NROWS * DIM]; // fp16 embeddings
__device__ float g_nrm8[(size_t)NROWS * 8];                 // per-(128col x nwarp) partial norms
__device__ float g_part[(size_t)NX * NSPLIT2 * D_OUT];

// ---------------- PTX helpers (base-sm_103 legal) ----------------
__device__ __forceinline__ uint32_t smem_u32(const void* p) {
    uint32_t a;
    asm("{ .reg .u64 t; cvta.to.shared.u64 t, %1; cvt.u32.u64 %0, t; }" : "=r"(a) : "l"(p));
    return a;
}
__device__ __forceinline__ void ldsm4(uint32_t& r0, uint32_t& r1, uint32_t& r2, uint32_t& r3, uint32_t a) {
    asm volatile("ldmatrix.sync.aligned.m8n8.x4.shared.b16 {%0,%1,%2,%3}, [%4];"
                 : "=r"(r0), "=r"(r1), "=r"(r2), "=r"(r3) : "r"(a));
}
__device__ __forceinline__ void mma16816(float* c, const uint32_t* a, const uint32_t* b) {
    asm volatile("mma.sync.aligned.m16n8k16.row.col.f32.f16.f16.f32 "
                 "{%0,%1,%2,%3}, {%4,%5,%6,%7}, {%8,%9}, {%0,%1,%2,%3};"
                 : "+f"(c[0]), "+f"(c[1]), "+f"(c[2]), "+f"(c[3])
                 : "r"(a[0]), "r"(a[1]), "r"(a[2]), "r"(a[3]), "r"(b[0]), "r"(b[1]));
}
__device__ __forceinline__ void cp16(uint32_t dst, const void* src) {
    asm volatile("cp.async.cg.shared.global [%0], [%1], 16;" :: "r"(dst), "l"(src));
}
#define CP_COMMIT() asm volatile("cp.async.commit_group;" ::: "memory")
#define CP_WAIT1()  asm volatile("cp.async.wait_group 1;" ::: "memory")

__device__ __forceinline__ uint32_t h2pack(float a, float b) {
    __half2 h = __floats2half2_rn(a, b);
    return *(uint32_t*)&h;
}

// fast sincos on the FMA pipe (abs err < 3e-8)
__device__ __forceinline__ void fsincos(float z, float* s, float* c) {
    const float t  = z * 0.6366197723675814f;
    const float qm = t + 12582912.0f;
    const float q  = qm - 12582912.0f;
    const int   iq = (int)__float_as_uint(qm) & 3;
    float r = fmaf(q, -1.57079637e+00f, z);
    r = fmaf(q, 4.3711388e-08f, r);
    const float r2 = r * r;
    float ps = fmaf(r2, fmaf(r2, fmaf(r2, fmaf(r2, 2.7557319e-6f, -1.9841270e-4f),
                    8.3333333e-3f), -1.6666667e-1f), 1.0f) * r;
    float pc = fmaf(r2, fmaf(r2, fmaf(r2, fmaf(r2, 2.4801587e-5f, -1.3888889e-3f),
                    4.1666667e-2f), -5.0e-1f), 1.0f);
    float ss = (iq & 1) ? pc : ps;
    float cc = (iq & 1) ? ps : pc;
    if (iq & 2) ss = -ss;
    if ((iq + 1) & 2) cc = -cc;
    *s = ss; *c = cc;
}

// stage one chunk: A 128 rows x 64B (512 cp16) + B 256 rows x 64B (1024 cp16)
// 1536 cp16 / 512 threads = 3 each; warps land wholly in A- or B-region
__device__ __forceinline__ void stageAB(uint32_t sbase, const char* gA, const char* gB,
                                        int str, int tid)
{
#pragma unroll
    for (int it = 0; it < 3; it++) {
        const int e = it * 512 + tid;
        if (e < 512) {
            const int r = e >> 2, s = e & 3;
            cp16(sbase + r * ROWSTR + s * 16, gA + (size_t)r * str + s * 16);
        } else {
            const int id = e - 512;
            const int r = id >> 2, s = id & 3;
            cp16(sbase + TILEA + r * ROWSTR + s * 16, gB + (size_t)r * str + s * 16);
        }
    }
}

// warp microkernel: m32 x n64 (4m x 4n warp grid => CTA tile 128 x 256)
// acc[0..7] = m-frag0 (rows mw*32+0..15), acc[8..15] = m-frag1 (+16..31)
__device__ __forceinline__ void gemm_step(uint32_t sbuf, float (*acc)[4],
                                          int mw, int nw, int lane)
{
    const uint32_t a0 = sbuf + (uint32_t)(mw * 32 + (lane & 15)) * ROWSTR
                      + ((uint32_t)(lane >> 4) & 1) * 16;
    const uint32_t a1 = a0 + 16 * ROWSTR;
    const uint32_t b0 = sbuf + TILEA
                      + (uint32_t)(nw * 64 + (lane & 7) + ((lane >> 4) << 3)) * ROWSTR
                      + ((uint32_t)(lane >> 3) & 1) * 16;
#pragma unroll
    for (int ks = 0; ks < 2; ks++) {
        const uint32_t kc = ks * 32;
        uint32_t ah0[4], ah1[4];
        ldsm4(ah0[0], ah0[1], ah0[2], ah0[3], a0 + kc);
        ldsm4(ah1[0], ah1[1], ah1[2], ah1[3], a1 + kc);
        uint32_t bh[16];
#pragma unroll
        for (int p = 0; p < 4; p++)
            ldsm4(bh[4*p], bh[4*p+1], bh[4*p+2], bh[4*p+3], b0 + kc + p * (16 * ROWSTR));
#pragma unroll
        for (int t = 0; t < 8; t++) {
            mma16816(acc[t],     ah0, &bh[2*t]);
            mma16816(acc[8 + t], ah1, &bh[2*t]);
        }
    }
}

// 3-stage, single-sync pipelined GEMM mainloop (K advances 64B per iter)
__device__ __forceinline__ void gemm_main(uint32_t sb, const char* gA, const char* gB,
                                          int str, int niter, float (*acc)[4],
                                          int mw, int nw, int lane, int tid)
{
    stageAB(sb, gA, gB, str, tid); CP_COMMIT();
    stageAB(sb + STAGEB, gA + 64, gB + 64, str, tid); CP_COMMIT();
    uint32_t bufs[3] = { sb, sb + STAGEB, sb + 2 * STAGEB };
    for (int kb = 0; kb < niter; kb++) {
        CP_WAIT1();
        __syncthreads();
        if (kb + 2 < niter)
            stageAB(bufs[(kb + 2) % 3], gA + (kb + 2) * 64, gB + (kb + 2) * 64, str, tid);
        CP_COMMIT();
        gemm_step(bufs[kb % 3], acc, mw, nw, lane);
    }
}

// =====================================================================
// Kernel 1: feature generation -> fp16 feature rows (HFMA2 MLP)
// =====================================================================
__global__ void __launch_bounds__(256)
featgen_kernel(const float* __restrict__ cx, const float* __restrict__ xx,
               const float* __restrict__ freq, const float* __restrict__ plr_w,
               const float* __restrict__ plr_b)
{
    __shared__ float    s_x[256 * 33];
    __shared__ float    s_fr[384];
    __shared__ uint32_t s_pw2[512];
    __shared__ uint32_t s_pb2[16];
    const int tid = threadIdx.x;
    const size_t rowBase = (size_t)blockIdx.x * 256;

    for (int i = tid; i < 384; i += 256) s_fr[i] = TWO_PI * freq[i];
    for (int i = tid; i < 512; i += 256) {
        const int e2 = i >> 5, f = i & 31;
        s_pw2[i] = h2pack(plr_w[(2 * e2) * 32 + f], plr_w[(2 * e2 + 1) * 32 + f]);
    }
    if (tid < 16) s_pb2[tid] = h2pack(plr_b[2 * tid], plr_b[2 * tid + 1]);
    for (int i = tid; i < 256 * 32; i += 256) {
        const int r = i >> 5, k = i & 31;
        const size_t gr = rowBase + r;
        float v = 0.f;
        if (gr < NC) v = cx[gr * D_IN + k];
        else if (gr >= NCPAD) v = xx[(gr - NCPAD) * D_IN + k];
        s_x[r * 33 + k] = v;
    }
    __syncthreads();

    const float* xs = s_x + tid * 33;
    __half* dst = g_fb + (rowBase + tid) * KF;
    const __half2 zero2 = __float2half2_rn(0.f);

    for (int n = 0; n < 24; n++) {
        const float v = xs[n];
        __half2 hc[16], hs[16];
#pragma unroll
        for (int f = 0; f < 16; f++) {
            float ss, cc;
            fsincos(s_fr[n * 16 + f] * v, &ss, &cc);
            hs[f] = __float2half2_rn(ss);
            hc[f] = __float2half2_rn(cc);
        }
        uint32_t W[16];
#pragma unroll 4
        for (int e2 = 0; e2 < 16; e2++) {
            __half2 acc2 = *(const __half2*)&s_pb2[e2];
            const __half2* pw = (const __half2*)&s_pw2[e2 * 32];
#pragma unroll
            for (int f = 0; f < 16; f++) {
                acc2 = __hfma2(hc[f], pw[f], acc2);
                acc2 = __hfma2(hs[f], pw[16 + f], acc2);
            }
            const __half2 r2 = __hmax2(acc2, zero2);
            W[e2] = *(const uint32_t*)&r2;
        }
        uint4* dq = (uint4*)((char*)dst + n * 64);
#pragma unroll
        for (int q = 0; q < 4; q++)
            dq[q] = make_uint4(W[4*q], W[4*q+1], W[4*q+2], W[4*q+3]);
    }
#pragma unroll 8
    for (int k = 0; k < 64; k++)
        dst[768 + k] = __float2half_rn((k < 8) ? xs[24 + k] : 0.f);
}

// =====================================================================
// Kernel 2: pack enc_w -> fp16
// =====================================================================
__global__ void wprep_kernel(const float* __restrict__ enc_w)
{
    const int idx = blockIdx.x * 256 + threadIdx.x;
    if (idx >= DIM * KF) return;
    const int n = idx / KF, k = idx % KF;
    g_wb[(size_t)n * KF + k] = __float2half_rn((k < 776) ? enc_w[n * 776 + k] : 0.f);
}

// =====================================================================
// Kernel 3: encode GEMM (128 rows x 256 cols, 512 thr), fused partial norms
// =====================================================================
__global__ void __launch_bounds__(512, 1)
enc_mma_kernel(const float* __restrict__ enc_b)
{
    extern __shared__ char sm[];
    __shared__ float s_bias[256];
    const uint32_t sb = smem_u32(sm);
    const int tid = threadIdx.x, wid = tid >> 5, lane = tid & 31;
    const int mw = wid >> 2, nw = wid & 3;
    const size_t rowBase = (size_t)blockIdx.x * 128;
    const int colBase = blockIdx.y * 256;
    if (tid < 256) s_bias[tid] = enc_b[colBase + tid];

    const char* gA = (const char*)(g_fb + rowBase * KF);
    const char* gB = (const char*)(g_wb + (size_t)colBase * KF);

    float acc[16][4];
#pragma unroll
    for (int t = 0; t < 16; t++)
#pragma unroll
        for (int u = 0; u < 4; u++) acc[t][u] = 0.f;

    gemm_main(sb, gA, gB, KF * 2, 26, acc, mw, nw, lane, tid);

    // epilogue: bias, fp16 store, quad-reduced partial norms (4 rows/thread)
    const int g = lane >> 2, tig = lane & 3;
    const int nslot = blockIdx.y * 4 + nw;      // 0..7
    float nrm[4] = {0.f, 0.f, 0.f, 0.f};
#pragma unroll
    for (int t = 0; t < 8; t++) {
        const int bcol = nw * 64 + t * 8 + tig * 2;
        const int col = colBase + bcol;
        const float b0 = s_bias[bcol], b1 = s_bias[bcol + 1];
        const float v00 = acc[t][0] + b0,     v01 = acc[t][1] + b1;
        const float v02 = acc[t][2] + b0,     v03 = acc[t][3] + b1;
        const float v10 = acc[8 + t][0] + b0, v11 = acc[8 + t][1] + b1;
        const float v12 = acc[8 + t][2] + b0, v13 = acc[8 + t][3] + b1;
        const size_t r = rowBase + mw * 32 + g;
        *(uint32_t*)(g_emb + r * DIM + col)        = h2pack(v00, v01);
        *(uint32_t*)(g_emb + (r + 8) * DIM + col)  = h2pack(v02, v03);
        *(uint32_t*)(g_emb + (r + 16) * DIM + col) = h2pack(v10, v11);
        *(uint32_t*)(g_emb + (r + 24) * DIM + col) = h2pack(v12, v13);
        nrm[0] = fmaf(v00, v00, fmaf(v01, v01, nrm[0]));
        nrm[1] = fmaf(v02, v02, fmaf(v03, v03, nrm[1]));
        nrm[2] = fmaf(v10, v10, fmaf(v11, v11, nrm[2]));
        nrm[3] = fmaf(v12, v12, fmaf(v13, v13, nrm[3]));
    }
#pragma unroll
    for (int i = 0; i < 4; i++) {
        nrm[i] += __shfl_xor_sync(0xffffffffu, nrm[i], 1);
        nrm[i] += __shfl_xor_sync(0xffffffffu, nrm[i], 2);
    }
    if (tig == 0) {
        const size_t r = rowBase + mw * 32 + g;
        g_nrm8[r * 8 + nslot]        = nrm[0];
        g_nrm8[(r + 8) * 8 + nslot]  = nrm[1];
        g_nrm8[(r + 16) * 8 + nslot] = nrm[2];
        g_nrm8[(r + 24) * 8 + nslot] = nrm[3];
    }
}

// =====================================================================
// Kernel 4: NCA GEMM (128 x-rows x 256 cands, 512 thr) + fused norm
// reduction + distance/exp/class partials
// =====================================================================
__global__ void __launch_bounds__(512, 1)
nca_mma_kernel(const int* __restrict__ cy)
{
    extern __shared__ char sm[];
    __shared__ float s_cn[256];
    __shared__ int   s_cy[256];
    __shared__ float s_xn[128];
    const uint32_t sb = smem_u32(sm);
    const int tid = threadIdx.x, wid = tid >> 5, lane = tid & 31;
    const int mw = wid >> 2, nw = wid & 3;
    const int xBase = blockIdx.x * 128;
    const int cBase = blockIdx.y * 256;

    // fold norm reduction into prologue (mainloop barriers order these stores)
    if (tid < 256) {
        const int j = cBase + tid;
        const float* p = g_nrm8 + (size_t)j * 8;
        float s = ((p[0] + p[1]) + (p[2] + p[3])) + ((p[4] + p[5]) + (p[6] + p[7]));
        s_cn[tid] = (j < NC) ? s : 1e30f;     // poison padded -> exp == 0
        s_cy[tid] = cy[min(j, NC - 1)];
    } else if (tid < 384) {
        const int r = NCPAD + xBase + (tid - 256);
        const float* p = g_nrm8 + (size_t)r * 8;
        s_xn[tid - 256] = ((p[0] + p[1]) + (p[2] + p[3])) + ((p[4] + p[5]) + (p[6] + p[7]));
    }

    const char* gA = (const char*)(g_emb + (size_t)(NCPAD + xBase) * DIM);
    const char* gB = (const char*)(g_emb + (size_t)cBase * DIM);

    float acc[16][4];
#pragma unroll
    for (int t = 0; t < 16; t++)
#pragma unroll
        for (int u = 0; u < 4; u++) acc[t][u] = 0.f;

    gemm_main(sb, gA, gB, DIM * 2, 16, acc, mw, nw, lane, tid);

    // epilogue: two sequential m-frag passes; scores <= 0 -> no online max
    const int g = lane >> 2, tig = lane & 3;
    const int slot = blockIdx.y * 4 + nw;     // 0..1599
#pragma unroll
    for (int mf = 0; mf < 2; mf++) {
        const int xr0 = xBase + mw * 32 + mf * 16 + g;
        const float xn0 = s_xn[xr0 - xBase];
        const float xn1 = s_xn[xr0 - xBase + 8];
        float n0[D_OUT], n1[D_OUT];
#pragma unroll
        for (int c = 0; c < D_OUT; c++) { n0[c] = 0.f; n1[c] = 0.f; }
#pragma unroll
        for (int t = 0; t < 8; t++) {
            const float* a = acc[mf * 8 + t];
#pragma unroll
            for (int u = 0; u < 2; u++) {
                const int col = nw * 64 + t * 8 + tig * 2 + u;
                const float cn = s_cn[col];
                const int   y  = s_cy[col];
                const float sq0 = fmaxf(xn0 + cn - 2.f * a[u],     1e-12f);
                const float sq1 = fmaxf(xn1 + cn - 2.f * a[2 + u], 1e-12f);
                const float e0 = __expf(-sqrtf(sq0));
                const float e1 = __expf(-sqrtf(sq1));
#pragma unroll
                for (int c = 0; c < D_OUT; c++) {
                    n0[c] += (y == c) ? e0 : 0.f;
                    n1[c] += (y == c) ? e1 : 0.f;
                }
            }
        }
#pragma unroll
        for (int c = 0; c < D_OUT; c++) {
            n0[c] += __shfl_xor_sync(0xffffffffu, n0[c], 1);
            n0[c] += __shfl_xor_sync(0xffffffffu, n0[c], 2);
            n1[c] += __shfl_xor_sync(0xffffffffu, n1[c], 1);
            n1[c] += __shfl_xor_sync(0xffffffffu, n1[c], 2);
        }
        if (tig == 0) {
            float* P0 = g_part + ((size_t)xr0 * NSPLIT2 + slot) * D_OUT;
            float* P1 = g_part + ((size_t)(xr0 + 8) * NSPLIT2 + slot) * D_OUT;
#pragma unroll
            for (int c = 0; c < D_OUT; c++) { P0[c] = n0[c]; P1[c] = n1[c]; }
        }
    }
}

// =====================================================================
// Kernel 5: reduce partials -> log-probs (warp per x row, deterministic)
// =====================================================================
__global__ void __launch_bounds__(256)
finalize_kernel(float* __restrict__ out)
{
    const int w = (blockIdx.x * 256 + threadIdx.x) >> 5;
    const int lane = threadIdx.x & 31;
    if (w >= NX) return;
    const float* P = g_part + (size_t)w * NSPLIT2 * D_OUT;
    float n[D_OUT];
#pragma unroll
    for (int c = 0; c < D_OUT; c++) n[c] = 0.f;
    for (int s = lane; s < NSPLIT2; s += 32) {
        const float* q = P + s * D_OUT;
#pragma unroll
        for (int c = 0; c < D_OUT; c++) n[c] += q[c];
    }
#pragma unroll
    for (int o = 16; o; o >>= 1)
#pragma unroll
        for (int c = 0; c < D_OUT; c++) n[c] += __shfl_xor_sync(0xffffffffu, n[c], o);
    if (lane == 0) {
        float l = 0.f;
#pragma unroll
        for (int c = 0; c < D_OUT; c++) l += n[c];
        const float inv = 1.0f / l;
#pragma unroll
        for (int c = 0; c < D_OUT; c++)
            out[w * D_OUT + c] = logf(n[c] * inv + 1e-7f);
    }
}

// =====================================================================
extern "C" void kernel_launch(void* const* d_in, const int* in_sizes, int n_in,
                              void* d_out, int out_size)
{
    const float* x     = (const float*)d_in[0];
    const float* cx    = (const float*)d_in[1];
    const int*   cy    = (const int*)d_in[2];
    const float* freq  = (const float*)d_in[3];
    const float* plr_w = (const float*)d_in[4];
    const float* plr_b = (const float*)d_in[5];
    const float* enc_w = (const float*)d_in[6];
    const float* enc_b = (const float*)d_in[7];
    float* out = (float*)d_out;

    cudaFuncSetAttribute(enc_mma_kernel, cudaFuncAttributeMaxDynamicSharedMemorySize, DYNSMEM);
    cudaFuncSetAttribute(nca_mma_kernel, cudaFuncAttributeMaxDynamicSharedMemorySize, DYNSMEM);

    featgen_kernel<<<NROWS / 256, 256>>>(cx, x, freq, plr_w, plr_b);
    wprep_kernel<<<(DIM * KF + 255) / 256, 256>>>(enc_w);
    enc_mma_kernel<<<dim3(NROWS / 128, DIM / 256), 512, DYNSMEM>>>(enc_b);
    nca_mma_kernel<<<dim3(NX / 128, NCPAD / 256), 512, DYNSMEM>>>(cy);
    finalize_kernel<<<(NX * 32) / 256, 256>>>(out);
}

// round 12
// speedup vs baseline: 1.3096x; 1.3096x over previous
#include <cuda_runtime.h>
#include <cuda_fp16.h>
#include <stdint.h>
#include <math.h>

#define D_IN     32
#define KF       832            // padded feature dim (26*32)
#define DIM      512
#define D_OUT    10
#define NX       1024
#define NC       100000
#define NCPAD    102400         // 800 * 128
#define NROWS    (NCPAD + NX)   // 103424 = 808*128
#define NSPLIT   800            // candidate blocks of 128
#define TWO_PI   6.283185307179586f

// stage geometry: K-chunk 32 halves (64B) per tile row, 80B padded stride
#define ROWSTR   80
#define TILEB    (128 * ROWSTR)     // 10240
#define STAGEB   (2 * TILEB)        // 20480 (A + B)
#define NSTAGE   3
#define DYNSMEM  (NSTAGE * STAGEB)  // 61440 -> 2 CTAs/SM by smem

// P tile (exp scores) reuses the ring: 128 rows x 272B stride (272 % 128 == 16
// -> conflict-free for both STS.32 and ldmatrix row patterns)
#define PSTR     272

// ---------------- device scratch (alloc-free) ----------------
__device__ __align__(16) __half g_fb[(size_t)NROWS * KF];   // fp16 feats
__device__ __align__(16) __half g_wb[(size_t)DIM * KF];     // fp16 enc_w
__device__ __align__(16) __half g_emb[(size_t)NROWS * DIM]; // fp16 embeddings
__device__ float g_nrm8[(size_t)NROWS * 8];                 // per-(128col x nwarp) partial norms
__device__ float g_part[(size_t)NX * NSPLIT * D_OUT];

// ---------------- PTX helpers (base-sm_103 legal) ----------------
__device__ __forceinline__ uint32_t smem_u32(const void* p) {
    uint32_t a;
    asm("{ .reg .u64 t; cvta.to.shared.u64 t, %1; cvt.u32.u64 %0, t; }" : "=r"(a) : "l"(p));
    return a;
}
__device__ __forceinline__ void ldsm4(uint32_t& r0, uint32_t& r1, uint32_t& r2, uint32_t& r3, uint32_t a) {
    asm volatile("ldmatrix.sync.aligned.m8n8.x4.shared.b16 {%0,%1,%2,%3}, [%4];"
                 : "=r"(r0), "=r"(r1), "=r"(r2), "=r"(r3) : "r"(a));
}
__device__ __forceinline__ void ldsm2(uint32_t& r0, uint32_t& r1, uint32_t a) {
    asm volatile("ldmatrix.sync.aligned.m8n8.x2.shared.b16 {%0,%1}, [%2];"
                 : "=r"(r0), "=r"(r1) : "r"(a));
}
__device__ __forceinline__ void mma16816(float* c, const uint32_t* a, const uint32_t* b) {
    asm volatile("mma.sync.aligned.m16n8k16.row.col.f32.f16.f16.f32 "
                 "{%0,%1,%2,%3}, {%4,%5,%6,%7}, {%8,%9}, {%0,%1,%2,%3};"
                 : "+f"(c[0]), "+f"(c[1]), "+f"(c[2]), "+f"(c[3])
                 : "r"(a[0]), "r"(a[1]), "r"(a[2]), "r"(a[3]), "r"(b[0]), "r"(b[1]));
}
__device__ __forceinline__ void cp16(uint32_t dst, const void* src) {
    asm volatile("cp.async.cg.shared.global [%0], [%1], 16;" :: "r"(dst), "l"(src));
}
#define CP_COMMIT() asm volatile("cp.async.commit_group;" ::: "memory")
#define CP_WAIT1()  asm volatile("cp.async.wait_group 1;" ::: "memory")

__device__ __forceinline__ uint32_t h2pack(float a, float b) {
    __half2 h = __floats2half2_rn(a, b);
    return *(uint32_t*)&h;
}

// fast sincos on the FMA pipe (abs err < 3e-8)
__device__ __forceinline__ void fsincos(float z, float* s, float* c) {
    const float t  = z * 0.6366197723675814f;
    const float qm = t + 12582912.0f;
    const float q  = qm - 12582912.0f;
    const int   iq = (int)__float_as_uint(qm) & 3;
    float r = fmaf(q, -1.57079637e+00f, z);
    r = fmaf(q, 4.3711388e-08f, r);
    const float r2 = r * r;
    float ps = fmaf(r2, fmaf(r2, fmaf(r2, fmaf(r2, 2.7557319e-6f, -1.9841270e-4f),
                    8.3333333e-3f), -1.6666667e-1f), 1.0f) * r;
    float pc = fmaf(r2, fmaf(r2, fmaf(r2, fmaf(r2, 2.4801587e-5f, -1.3888889e-3f),
                    4.1666667e-2f), -5.0e-1f), 1.0f);
    float ss = (iq & 1) ? pc : ps;
    float cc = (iq & 1) ? ps : pc;
    if (iq & 2) ss = -ss;
    if ((iq + 1) & 2) cc = -cc;
    *s = ss; *c = cc;
}

// stage one 128-row x 64-byte chunk for A and B: 1024 cp16 / 256 thr = 4 each
__device__ __forceinline__ void stageAB(uint32_t sbase, const char* gA, const char* gB,
                                        int str, int tid)
{
#pragma unroll
    for (int it = 0; it < 4; it++) {
        const int e   = it * 256 + tid;
        const int isB = e >> 9;
        const int id  = e & 511;
        const int r   = id >> 2;
        const int s   = id & 3;
        const char* g = isB ? gB : gA;
        cp16(sbase + isB * TILEB + r * ROWSTR + s * 16, g + (size_t)r * str + s * 16);
    }
}

// warp microkernel: m32 x n64 (4m x 2n warp grid) over one 32-wide K chunk
__device__ __forceinline__ void gemm_step(uint32_t sbuf, float (*acc)[4],
                                          int mw, int nw, int lane)
{
    const uint32_t a0 = sbuf + (uint32_t)(mw * 32 + (lane & 15)) * ROWSTR
                      + ((uint32_t)(lane >> 4) & 1) * 16;
    const uint32_t a1 = a0 + 16 * ROWSTR;
    const uint32_t b0 = sbuf + TILEB
                      + (uint32_t)(nw * 64 + (lane & 7) + ((lane >> 4) << 3)) * ROWSTR
                      + ((uint32_t)(lane >> 3) & 1) * 16;
#pragma unroll
    for (int ks = 0; ks < 2; ks++) {
        const uint32_t kc = ks * 32;
        uint32_t ah0[4], ah1[4];
        ldsm4(ah0[0], ah0[1], ah0[2], ah0[3], a0 + kc);
        ldsm4(ah1[0], ah1[1], ah1[2], ah1[3], a1 + kc);
        uint32_t bh[16];
#pragma unroll
        for (int p = 0; p < 4; p++)
            ldsm4(bh[4*p], bh[4*p+1], bh[4*p+2], bh[4*p+3], b0 + kc + p * (16 * ROWSTR));
#pragma unroll
        for (int t = 0; t < 8; t++) {
            mma16816(acc[t],     ah0, &bh[2*t]);
            mma16816(acc[8 + t], ah1, &bh[2*t]);
        }
    }
}

// 3-stage, single-sync pipelined GEMM mainloop (K advances 64B per iter)
__device__ __forceinline__ void gemm_main(uint32_t sb, const char* gA, const char* gB,
                                          int str, int niter, float (*acc)[4],
                                          int mw, int nw, int lane, int tid)
{
    stageAB(sb, gA, gB, str, tid); CP_COMMIT();
    stageAB(sb + STAGEB, gA + 64, gB + 64, str, tid); CP_COMMIT();
    uint32_t bufs[3] = { sb, sb + STAGEB, sb + 2 * STAGEB };
    for (int kb = 0; kb < niter; kb++) {
        CP_WAIT1();
        __syncthreads();
        if (kb + 2 < niter)
            stageAB(bufs[(kb + 2) % 3], gA + (kb + 2) * 64, gB + (kb + 2) * 64, str, tid);
        CP_COMMIT();
        gemm_step(bufs[kb % 3], acc, mw, nw, lane);
    }
}

// =====================================================================
// Kernel 1: feature generation -> fp16 feature rows (HFMA2 MLP)
// =====================================================================
__global__ void __launch_bounds__(256)
featgen_kernel(const float* __restrict__ cx, const float* __restrict__ xx,
               const float* __restrict__ freq, const float* __restrict__ plr_w,
               const float* __restrict__ plr_b)
{
    __shared__ float    s_x[256 * 33];
    __shared__ float    s_fr[384];
    __shared__ uint32_t s_pw2[512];
    __shared__ uint32_t s_pb2[16];
    const int tid = threadIdx.x;
    const size_t rowBase = (size_t)blockIdx.x * 256;

    for (int i = tid; i < 384; i += 256) s_fr[i] = TWO_PI * freq[i];
    for (int i = tid; i < 512; i += 256) {
        const int e2 = i >> 5, f = i & 31;
        s_pw2[i] = h2pack(plr_w[(2 * e2) * 32 + f], plr_w[(2 * e2 + 1) * 32 + f]);
    }
    if (tid < 16) s_pb2[tid] = h2pack(plr_b[2 * tid], plr_b[2 * tid + 1]);
    for (int i = tid; i < 256 * 32; i += 256) {
        const int r = i >> 5, k = i & 31;
        const size_t gr = rowBase + r;
        float v = 0.f;
        if (gr < NC) v = cx[gr * D_IN + k];
        else if (gr >= NCPAD) v = xx[(gr - NCPAD) * D_IN + k];
        s_x[r * 33 + k] = v;
    }
    __syncthreads();

    const float* xs = s_x + tid * 33;
    __half* dst = g_fb + (rowBase + tid) * KF;
    const __half2 zero2 = __float2half2_rn(0.f);

    for (int n = 0; n < 24; n++) {
        const float v = xs[n];
        __half2 hc[16], hs[16];
#pragma unroll
        for (int f = 0; f < 16; f++) {
            float ss, cc;
            fsincos(s_fr[n * 16 + f] * v, &ss, &cc);
            hs[f] = __float2half2_rn(ss);
            hc[f] = __float2half2_rn(cc);
        }
        uint32_t W[16];
#pragma unroll 4
        for (int e2 = 0; e2 < 16; e2++) {
            __half2 acc2 = *(const __half2*)&s_pb2[e2];
            const __half2* pw = (const __half2*)&s_pw2[e2 * 32];
#pragma unroll
            for (int f = 0; f < 16; f++) {
                acc2 = __hfma2(hc[f], pw[f], acc2);
                acc2 = __hfma2(hs[f], pw[16 + f], acc2);
            }
            const __half2 r2 = __hmax2(acc2, zero2);
            W[e2] = *(const uint32_t*)&r2;
        }
        uint4* dq = (uint4*)((char*)dst + n * 64);
#pragma unroll
        for (int q = 0; q < 4; q++)
            dq[q] = make_uint4(W[4*q], W[4*q+1], W[4*q+2], W[4*q+3]);
    }
#pragma unroll 8
    for (int k = 0; k < 64; k++)
        dst[768 + k] = __float2half_rn((k < 8) ? xs[24 + k] : 0.f);
}

// =====================================================================
// Kernel 2: pack enc_w -> fp16
// =====================================================================
__global__ void wprep_kernel(const float* __restrict__ enc_w)
{
    const int idx = blockIdx.x * 256 + threadIdx.x;
    if (idx >= DIM * KF) return;
    const int n = idx / KF, k = idx % KF;
    g_wb[(size_t)n * KF + k] = __float2half_rn((k < 776) ? enc_w[n * 776 + k] : 0.f);
}

// =====================================================================
// Kernel 3: encode GEMM (128 rows x 128 cols), fused partial norms
// =====================================================================
__global__ void __launch_bounds__(256, 2)
enc_mma_kernel(const float* __restrict__ enc_b)
{
    extern __shared__ char sm[];
    __shared__ float s_bias[128];
    const uint32_t sb = smem_u32(sm);
    const int tid = threadIdx.x, wid = tid >> 5, lane = tid & 31;
    const int mw = wid >> 1, nw = wid & 1;
    const size_t rowBase = (size_t)blockIdx.x * 128;
    const int colBase = blockIdx.y * 128;
    if (tid < 128) s_bias[tid] = enc_b[colBase + tid];

    const char* gA = (const char*)(g_fb + rowBase * KF);
    const char* gB = (const char*)(g_wb + (size_t)colBase * KF);

    float acc[16][4];
#pragma unroll
    for (int t = 0; t < 16; t++)
#pragma unroll
        for (int u = 0; u < 4; u++) acc[t][u] = 0.f;

    gemm_main(sb, gA, gB, KF * 2, 26, acc, mw, nw, lane, tid);

    // epilogue: bias, fp16 store, quad-reduced partial norms (4 rows/thread)
    const int g = lane >> 2, tig = lane & 3;
    const int nslot = blockIdx.y * 2 + nw;      // 0..7
    float nrm[4] = {0.f, 0.f, 0.f, 0.f};
#pragma unroll
    for (int t = 0; t < 8; t++) {
        const int bcol = nw * 64 + t * 8 + tig * 2;
        const int col = colBase + bcol;
        const float b0 = s_bias[bcol], b1 = s_bias[bcol + 1];
        const float v00 = acc[t][0] + b0,     v01 = acc[t][1] + b1;
        const float v02 = acc[t][2] + b0,     v03 = acc[t][3] + b1;
        const float v10 = acc[8 + t][0] + b0, v11 = acc[8 + t][1] + b1;
        const float v12 = acc[8 + t][2] + b0, v13 = acc[8 + t][3] + b1;
        const size_t r = rowBase + mw * 32 + g;
        *(uint32_t*)(g_emb + r * DIM + col)        = h2pack(v00, v01);
        *(uint32_t*)(g_emb + (r + 8) * DIM + col)  = h2pack(v02, v03);
        *(uint32_t*)(g_emb + (r + 16) * DIM + col) = h2pack(v10, v11);
        *(uint32_t*)(g_emb + (r + 24) * DIM + col) = h2pack(v12, v13);
        nrm[0] = fmaf(v00, v00, fmaf(v01, v01, nrm[0]));
        nrm[1] = fmaf(v02, v02, fmaf(v03, v03, nrm[1]));
        nrm[2] = fmaf(v10, v10, fmaf(v11, v11, nrm[2]));
        nrm[3] = fmaf(v12, v12, fmaf(v13, v13, nrm[3]));
    }
#pragma unroll
    for (int i = 0; i < 4; i++) {
        nrm[i] += __shfl_xor_sync(0xffffffffu, nrm[i], 1);
        nrm[i] += __shfl_xor_sync(0xffffffffu, nrm[i], 2);
    }
    if (tig == 0) {
        const size_t r = rowBase + mw * 32 + g;
        g_nrm8[r * 8 + nslot]        = nrm[0];
        g_nrm8[(r + 8) * 8 + nslot]  = nrm[1];
        g_nrm8[(r + 16) * 8 + nslot] = nrm[2];
        g_nrm8[(r + 24) * 8 + nslot] = nrm[3];
    }
}

// =====================================================================
// Kernel 4: NCA GEMM + exp + one-hot class MMA epilogue
// grid (NX/128, NCPAD/128)
// =====================================================================
__global__ void __launch_bounds__(256, 2)
nca_mma_kernel(const int* __restrict__ cy)
{
    extern __shared__ char sm[];
    __shared__ float s_cn[128];
    __shared__ int   s_cy[128];
    __shared__ float s_xn[128];
    __shared__ __align__(16) __half s_oh[16 * 136];   // one-hot [class][cand], 272B stride
    const uint32_t sb = smem_u32(sm);
    const int tid = threadIdx.x, wid = tid >> 5, lane = tid & 31;
    const int mw = wid >> 1, nw = wid & 1;
    const int xBase = blockIdx.x * 128;
    const int cBase = blockIdx.y * 128;

    // prologue: fold norm8 reduction; poison padded cands (exp -> 0)
    if (tid < 128) {
        const int j = cBase + tid;
        const float* p = g_nrm8 + (size_t)j * 8;
        const float s = ((p[0] + p[1]) + (p[2] + p[3])) + ((p[4] + p[5]) + (p[6] + p[7]));
        s_cn[tid] = (j < NC) ? s : 1e30f;
        s_cy[tid] = cy[min(j, NC - 1)];
    } else {
        const int r = NCPAD + xBase + (tid - 128);
        const float* p = g_nrm8 + (size_t)r * 8;
        s_xn[tid - 128] = ((p[0] + p[1]) + (p[2] + p[3])) + ((p[4] + p[5]) + (p[6] + p[7]));
    }

    const char* gA = (const char*)(g_emb + (size_t)(NCPAD + xBase) * DIM);
    const char* gB = (const char*)(g_emb + (size_t)cBase * DIM);

    float acc[16][4];
#pragma unroll
    for (int t = 0; t < 16; t++)
#pragma unroll
        for (int u = 0; u < 4; u++) acc[t][u] = 0.f;

    gemm_main(sb, gA, gB, DIM * 2, 16, acc, mw, nw, lane, tid);

    __syncthreads();   // ring buffers no longer read; reuse as P tile

    // build one-hot tile (classes 10..15 stay zero-padded)
    if (tid < 128) {
        const int y = s_cy[tid];
#pragma unroll
        for (int c = 0; c < 16; c++)
            s_oh[c * 136 + tid] = (y == c) ? __float2half(1.f) : __float2half(0.f);
    }

    // scores -> e = exp(-dist) -> fp16 P tile (scores <= 0, no max needed)
    const int g = lane >> 2, tig = lane & 3;
    float xnr[4];
#pragma unroll
    for (int i = 0; i < 4; i++) xnr[i] = s_xn[mw * 32 + 8 * i + g];
#pragma unroll
    for (int t = 0; t < 16; t++) {
        const int rhalf = t >> 3;
        const int col = nw * 64 + (t & 7) * 8 + tig * 2;
        const float cn0 = s_cn[col], cn1 = s_cn[col + 1];
        float e[4];
#pragma unroll
        for (int u = 0; u < 4; u++) {
            const float xn = xnr[rhalf * 2 + (u >> 1)];
            const float cn = (u & 1) ? cn1 : cn0;
            const float sq = fmaxf(xn + cn - 2.f * acc[t][u], 1e-12f);
            float d;
            asm("sqrt.approx.f32 %0, %1;" : "=f"(d) : "f"(sq));
            e[u] = __expf(-d);
        }
        const int row0 = mw * 32 + rhalf * 16 + g;
        *(uint32_t*)(sm + row0 * PSTR + col * 2)       = h2pack(e[0], e[1]);
        *(uint32_t*)(sm + (row0 + 8) * PSTR + col * 2) = h2pack(e[2], e[3]);
    }
    __syncthreads();

    // class GEMM: D[128 rows x 16 classes] = P(128x128) @ onehot^T, fp32 accum
    float d0[4] = {0.f, 0.f, 0.f, 0.f};
    float d1[4] = {0.f, 0.f, 0.f, 0.f};
    const uint32_t arow = sb + (uint32_t)(wid * 16 + (lane & 15)) * PSTR
                        + ((uint32_t)(lane >> 4)) * 16;
    const uint32_t ohb  = smem_u32(s_oh) + (uint32_t)(lane & 7) * PSTR
                        + ((uint32_t)((lane >> 3) & 1)) * 16;
#pragma unroll
    for (int ks = 0; ks < 8; ks++) {
        uint32_t a4[4];
        ldsm4(a4[0], a4[1], a4[2], a4[3], arow + ks * 32);
        uint32_t b0[2], b1[2];
        ldsm2(b0[0], b0[1], ohb + ks * 32);
        ldsm2(b1[0], b1[1], ohb + 8 * PSTR + ks * 32);
        mma16816(d0, a4, b0);
        mma16816(d1, a4, b1);
    }
    {
        float* P0 = g_part + ((size_t)(xBase + wid * 16 + g) * NSPLIT + blockIdx.y) * D_OUT;
        float* P1 = g_part + ((size_t)(xBase + wid * 16 + 8 + g) * NSPLIT + blockIdx.y) * D_OUT;
        P0[tig * 2]     = d0[0];
        P0[tig * 2 + 1] = d0[1];
        P1[tig * 2]     = d0[2];
        P1[tig * 2 + 1] = d0[3];
        if (tig == 0) {
            P0[8] = d1[0]; P0[9] = d1[1];
            P1[8] = d1[2]; P1[9] = d1[3];
        }
    }
}

// =====================================================================
// Kernel 5: reduce partials -> log-probs (warp per x row, deterministic)
// =====================================================================
__global__ void __launch_bounds__(256)
finalize_kernel(float* __restrict__ out)
{
    const int w = (blockIdx.x * 256 + threadIdx.x) >> 5;
    const int lane = threadIdx.x & 31;
    if (w >= NX) return;
    const float* P = g_part + (size_t)w * NSPLIT * D_OUT;
    float n[D_OUT];
#pragma unroll
    for (int c = 0; c < D_OUT; c++) n[c] = 0.f;
    for (int s = lane; s < NSPLIT; s += 32) {
        const float* q = P + s * D_OUT;
#pragma unroll
        for (int c = 0; c < D_OUT; c++) n[c] += q[c];
    }
#pragma unroll
    for (int o = 16; o; o >>= 1)
#pragma unroll
        for (int c = 0; c < D_OUT; c++) n[c] += __shfl_xor_sync(0xffffffffu, n[c], o);
    if (lane == 0) {
        float l = 0.f;
#pragma unroll
        for (int c = 0; c < D_OUT; c++) l += n[c];
        const float inv = 1.0f / l;
#pragma unroll
        for (int c = 0; c < D_OUT; c++)
            out[w * D_OUT + c] = logf(n[c] * inv + 1e-7f);
    }
}

// =====================================================================
extern "C" void kernel_launch(void* const* d_in, const int* in_sizes, int n_in,
                              void* d_out, int out_size)
{
    const float* x     = (const float*)d_in[0];
    const float* cx    = (const float*)d_in[1];
    const int*   cy    = (const int*)d_in[2];
    const float* freq  = (const float*)d_in[3];
    const float* plr_w = (const float*)d_in[4];
    const float* plr_b = (const float*)d_in[5];
    const float* enc_w = (const float*)d_in[6];
    const float* enc_b = (const float*)d_in[7];
    float* out = (float*)d_out;

    cudaFuncSetAttribute(enc_mma_kernel, cudaFuncAttributeMaxDynamicSharedMemorySize, DYNSMEM);
    cudaFuncSetAttribute(nca_mma_kernel, cudaFuncAttributeMaxDynamicSharedMemorySize, DYNSMEM);

    featgen_kernel<<<NROWS / 256, 256>>>(cx, x, freq, plr_w, plr_b);
    wprep_kernel<<<(DIM * KF + 255) / 256, 256>>>(enc_w);
    enc_mma_kernel<<<dim3(NROWS / 128, DIM / 128), 256, DYNSMEM>>>(enc_b);
    nca_mma_kernel<<<dim3(NX / 128, NCPAD / 128), 256, DYNSMEM>>>(cy);
    finalize_kernel<<<(NX * 32) / 256, 256>>>(out);
}

// round 13
// speedup vs baseline: 1.4188x; 1.0833x over previous
#include <cuda_runtime.h>
#include <cuda_fp16.h>
#include <stdint.h>
#include <math.h>

#define D_IN     32
#define KF       832            // padded feature dim (13*64)
#define DIM      512
#define D_OUT    10
#define NX       1024
#define NC       100000
#define NCPAD    102400         // 800 * 128
#define NROWS    (NCPAD + NX)   // 103424 = 808*128
#define NSPLIT   800            // candidate blocks of 128
#define TWO_PI   6.283185307179586f

// stage geometry: K-chunk 64 halves (128B) per tile row, 144B padded stride
#define ROWSTR   144
#define TILEB    (128 * ROWSTR)     // 18432
#define STAGEB   (2 * TILEB)        // 36864 (A + B)
#define NSTAGE   2
#define DYNSMEM  (NSTAGE * STAGEB)  // 73728 -> 2 CTAs/SM by smem

// P tile (exp scores) reuses the ring: 128 rows x 272B stride
#define PSTR     272

// ---------------- device scratch (alloc-free) ----------------
__device__ __align__(16) __half g_fb[(size_t)NROWS * KF];   // fp16 feats
__device__ __align__(16) __half g_wb[(size_t)DIM * KF];     // fp16 enc_w
__device__ __align__(16) __half g_emb[(size_t)NROWS * DIM]; // fp16 embeddings
__device__ float g_nrm8[(size_t)NROWS * 8];                 // per-(128col x nwarp) partial norms
__device__ float g_part[(size_t)NX * NSPLIT * D_OUT];

// ---------------- PTX helpers (base-sm_103 legal) ----------------
__device__ __forceinline__ uint32_t smem_u32(const void* p) {
    uint32_t a;
    asm("{ .reg .u64 t; cvta.to.shared.u64 t, %1; cvt.u32.u64 %0, t; }" : "=r"(a) : "l"(p));
    return a;
}
__device__ __forceinline__ void ldsm4(uint32_t& r0, uint32_t& r1, uint32_t& r2, uint32_t& r3, uint32_t a) {
    asm volatile("ldmatrix.sync.aligned.m8n8.x4.shared.b16 {%0,%1,%2,%3}, [%4];"
                 : "=r"(r0), "=r"(r1), "=r"(r2), "=r"(r3) : "r"(a));
}
__device__ __forceinline__ void ldsm2(uint32_t& r0, uint32_t& r1, uint32_t a) {
    asm volatile("ldmatrix.sync.aligned.m8n8.x2.shared.b16 {%0,%1}, [%2];"
                 : "=r"(r0), "=r"(r1) : "r"(a));
}
__device__ __forceinline__ void mma16816(float* c, const uint32_t* a, const uint32_t* b) {
    asm volatile("mma.sync.aligned.m16n8k16.row.col.f32.f16.f16.f32 "
                 "{%0,%1,%2,%3}, {%4,%5,%6,%7}, {%8,%9}, {%0,%1,%2,%3};"
                 : "+f"(c[0]), "+f"(c[1]), "+f"(c[2]), "+f"(c[3])
                 : "r"(a[0]), "r"(a[1]), "r"(a[2]), "r"(a[3]), "r"(b[0]), "r"(b[1]));
}
__device__ __forceinline__ void cp16(uint32_t dst, const void* src) {
    asm volatile("cp.async.cg.shared.global [%0], [%1], 16;" :: "r"(dst), "l"(src));
}
#define CP_COMMIT() asm volatile("cp.async.commit_group;" ::: "memory")
#define CP_WAIT0()  asm volatile("cp.async.wait_group 0;" ::: "memory")

__device__ __forceinline__ uint32_t h2pack(float a, float b) {
    __half2 h = __floats2half2_rn(a, b);
    return *(uint32_t*)&h;
}

// fast sincos on the FMA pipe (abs err < 3e-8)
__device__ __forceinline__ void fsincos(float z, float* s, float* c) {
    const float t  = z * 0.6366197723675814f;
    const float qm = t + 12582912.0f;
    const float q  = qm - 12582912.0f;
    const int   iq = (int)__float_as_uint(qm) & 3;
    float r = fmaf(q, -1.57079637e+00f, z);
    r = fmaf(q, 4.3711388e-08f, r);
    const float r2 = r * r;
    float ps = fmaf(r2, fmaf(r2, fmaf(r2, fmaf(r2, 2.7557319e-6f, -1.9841270e-4f),
                    8.3333333e-3f), -1.6666667e-1f), 1.0f) * r;
    float pc = fmaf(r2, fmaf(r2, fmaf(r2, fmaf(r2, 2.4801587e-5f, -1.3888889e-3f),
                    4.1666667e-2f), -5.0e-1f), 1.0f);
    float ss = (iq & 1) ? pc : ps;
    float cc = (iq & 1) ? ps : pc;
    if (iq & 2) ss = -ss;
    if ((iq + 1) & 2) cc = -cc;
    *s = ss; *c = cc;
}

// stage one 128-row x 128-byte chunk for A and B: 2048 cp16 / 256 thr = 8 each
__device__ __forceinline__ void stageAB(uint32_t sbase, const char* gA, const char* gB,
                                        int str, int tid)
{
#pragma unroll
    for (int it = 0; it < 8; it++) {
        const int e   = it * 256 + tid;
        const int isB = e >> 10;
        const int id  = e & 1023;
        const int r   = id >> 3;
        const int s   = id & 7;
        const char* g = isB ? gB : gA;
        cp16(sbase + isB * TILEB + r * ROWSTR + s * 16, g + (size_t)r * str + s * 16);
    }
}

// warp microkernel: m32 x n64 (4m x 2n warp grid) over one 64-wide K chunk
__device__ __forceinline__ void gemm_step(uint32_t sbuf, float (*acc)[4],
                                          int mw, int nw, int lane)
{
    const uint32_t a0 = sbuf + (uint32_t)(mw * 32 + (lane & 15)) * ROWSTR
                      + ((uint32_t)(lane >> 4) & 1) * 16;
    const uint32_t a1 = a0 + 16 * ROWSTR;
    const uint32_t b0 = sbuf + TILEB
                      + (uint32_t)(nw * 64 + (lane & 7) + ((lane >> 4) << 3)) * ROWSTR
                      + ((uint32_t)(lane >> 3) & 1) * 16;
#pragma unroll
    for (int ks = 0; ks < 4; ks++) {
        const uint32_t kc = ks * 32;
        uint32_t ah0[4], ah1[4];
        ldsm4(ah0[0], ah0[1], ah0[2], ah0[3], a0 + kc);
        ldsm4(ah1[0], ah1[1], ah1[2], ah1[3], a1 + kc);
        uint32_t bh[16];
#pragma unroll
        for (int p = 0; p < 4; p++)
            ldsm4(bh[4*p], bh[4*p+1], bh[4*p+2], bh[4*p+3], b0 + kc + p * (16 * ROWSTR));
#pragma unroll
        for (int t = 0; t < 8; t++) {
            mma16816(acc[t],     ah0, &bh[2*t]);
            mma16816(acc[8 + t], ah1, &bh[2*t]);
        }
    }
}

// 2-stage, single-sync pipelined mainloop (K advances 128B per iter).
// Stage of chunk kb+1 sits AFTER sync(kb): every thread passed sync(kb) only
// after finishing compute(kb-1), so the buffer being overwritten is idle.
__device__ __forceinline__ void gemm_main(uint32_t sb, const char* gA, const char* gB,
                                          int str, int niter, float (*acc)[4],
                                          int mw, int nw, int lane, int tid)
{
    stageAB(sb, gA, gB, str, tid); CP_COMMIT();
    uint32_t bufs[2] = { sb, sb + STAGEB };
    for (int kb = 0; kb < niter; kb++) {
        CP_WAIT0();
        __syncthreads();
        if (kb + 1 < niter) {
            stageAB(bufs[(kb + 1) & 1], gA + (kb + 1) * 128, gB + (kb + 1) * 128, str, tid);
            CP_COMMIT();
        }
        gemm_step(bufs[kb & 1], acc, mw, nw, lane);
    }
}

// =====================================================================
// Kernel 1: feature generation -> fp16 feature rows (HFMA2 MLP)
// =====================================================================
__global__ void __launch_bounds__(256)
featgen_kernel(const float* __restrict__ cx, const float* __restrict__ xx,
               const float* __restrict__ freq, const float* __restrict__ plr_w,
               const float* __restrict__ plr_b)
{
    __shared__ float    s_x[256 * 33];
    __shared__ float    s_fr[384];
    __shared__ uint32_t s_pw2[512];
    __shared__ uint32_t s_pb2[16];
    const int tid = threadIdx.x;
    const size_t rowBase = (size_t)blockIdx.x * 256;

    for (int i = tid; i < 384; i += 256) s_fr[i] = TWO_PI * freq[i];
    for (int i = tid; i < 512; i += 256) {
        const int e2 = i >> 5, f = i & 31;
        s_pw2[i] = h2pack(plr_w[(2 * e2) * 32 + f], plr_w[(2 * e2 + 1) * 32 + f]);
    }
    if (tid < 16) s_pb2[tid] = h2pack(plr_b[2 * tid], plr_b[2 * tid + 1]);
    for (int i = tid; i < 256 * 32; i += 256) {
        const int r = i >> 5, k = i & 31;
        const size_t gr = rowBase + r;
        float v = 0.f;
        if (gr < NC) v = cx[gr * D_IN + k];
        else if (gr >= NCPAD) v = xx[(gr - NCPAD) * D_IN + k];
        s_x[r * 33 + k] = v;
    }
    __syncthreads();

    const float* xs = s_x + tid * 33;
    __half* dst = g_fb + (rowBase + tid) * KF;
    const __half2 zero2 = __float2half2_rn(0.f);

    for (int n = 0; n < 24; n++) {
        const float v = xs[n];
        __half2 hc[16], hs[16];
#pragma unroll
        for (int f = 0; f < 16; f++) {
            float ss, cc;
            fsincos(s_fr[n * 16 + f] * v, &ss, &cc);
            hs[f] = __float2half2_rn(ss);
            hc[f] = __float2half2_rn(cc);
        }
        uint32_t W[16];
#pragma unroll 4
        for (int e2 = 0; e2 < 16; e2++) {
            __half2 acc2 = *(const __half2*)&s_pb2[e2];
            const __half2* pw = (const __half2*)&s_pw2[e2 * 32];
#pragma unroll
            for (int f = 0; f < 16; f++) {
                acc2 = __hfma2(hc[f], pw[f], acc2);
                acc2 = __hfma2(hs[f], pw[16 + f], acc2);
            }
            const __half2 r2 = __hmax2(acc2, zero2);
            W[e2] = *(const uint32_t*)&r2;
        }
        uint4* dq = (uint4*)((char*)dst + n * 64);
#pragma unroll
        for (int q = 0; q < 4; q++)
            dq[q] = make_uint4(W[4*q], W[4*q+1], W[4*q+2], W[4*q+3]);
    }
#pragma unroll 8
    for (int k = 0; k < 64; k++)
        dst[768 + k] = __float2half_rn((k < 8) ? xs[24 + k] : 0.f);
}

// =====================================================================
// Kernel 2: pack enc_w -> fp16
// =====================================================================
__global__ void wprep_kernel(const float* __restrict__ enc_w)
{
    const int idx = blockIdx.x * 256 + threadIdx.x;
    if (idx >= DIM * KF) return;
    const int n = idx / KF, k = idx % KF;
    g_wb[(size_t)n * KF + k] = __float2half_rn((k < 776) ? enc_w[n * 776 + k] : 0.f);
}

// =====================================================================
// Kernel 3: encode GEMM (128 rows x 128 cols), fused partial norms
// =====================================================================
__global__ void __launch_bounds__(256, 2)
enc_mma_kernel(const float* __restrict__ enc_b)
{
    extern __shared__ char sm[];
    __shared__ float s_bias[128];
    const uint32_t sb = smem_u32(sm);
    const int tid = threadIdx.x, wid = tid >> 5, lane = tid & 31;
    const int mw = wid >> 1, nw = wid & 1;
    const size_t rowBase = (size_t)blockIdx.x * 128;
    const int colBase = blockIdx.y * 128;
    if (tid < 128) s_bias[tid] = enc_b[colBase + tid];

    const char* gA = (const char*)(g_fb + rowBase * KF);
    const char* gB = (const char*)(g_wb + (size_t)colBase * KF);

    float acc[16][4];
#pragma unroll
    for (int t = 0; t < 16; t++)
#pragma unroll
        for (int u = 0; u < 4; u++) acc[t][u] = 0.f;

    gemm_main(sb, gA, gB, KF * 2, 13, acc, mw, nw, lane, tid);

    // epilogue: bias, fp16 store, quad-reduced partial norms (4 rows/thread)
    const int g = lane >> 2, tig = lane & 3;
    const int nslot = blockIdx.y * 2 + nw;      // 0..7
    float nrm[4] = {0.f, 0.f, 0.f, 0.f};
#pragma unroll
    for (int t = 0; t < 8; t++) {
        const int bcol = nw * 64 + t * 8 + tig * 2;
        const int col = colBase + bcol;
        const float b0 = s_bias[bcol], b1 = s_bias[bcol + 1];
        const float v00 = acc[t][0] + b0,     v01 = acc[t][1] + b1;
        const float v02 = acc[t][2] + b0,     v03 = acc[t][3] + b1;
        const float v10 = acc[8 + t][0] + b0, v11 = acc[8 + t][1] + b1;
        const float v12 = acc[8 + t][2] + b0, v13 = acc[8 + t][3] + b1;
        const size_t r = rowBase + mw * 32 + g;
        *(uint32_t*)(g_emb + r * DIM + col)        = h2pack(v00, v01);
        *(uint32_t*)(g_emb + (r + 8) * DIM + col)  = h2pack(v02, v03);
        *(uint32_t*)(g_emb + (r + 16) * DIM + col) = h2pack(v10, v11);
        *(uint32_t*)(g_emb + (r + 24) * DIM + col) = h2pack(v12, v13);
        nrm[0] = fmaf(v00, v00, fmaf(v01, v01, nrm[0]));
        nrm[1] = fmaf(v02, v02, fmaf(v03, v03, nrm[1]));
        nrm[2] = fmaf(v10, v10, fmaf(v11, v11, nrm[2]));
        nrm[3] = fmaf(v12, v12, fmaf(v13, v13, nrm[3]));
    }
#pragma unroll
    for (int i = 0; i < 4; i++) {
        nrm[i] += __shfl_xor_sync(0xffffffffu, nrm[i], 1);
        nrm[i] += __shfl_xor_sync(0xffffffffu, nrm[i], 2);
    }
    if (tig == 0) {
        const size_t r = rowBase + mw * 32 + g;
        g_nrm8[r * 8 + nslot]        = nrm[0];
        g_nrm8[(r + 8) * 8 + nslot]  = nrm[1];
        g_nrm8[(r + 16) * 8 + nslot] = nrm[2];
        g_nrm8[(r + 24) * 8 + nslot] = nrm[3];
    }
}

// =====================================================================
// Kernel 4: NCA GEMM + exp + one-hot class MMA epilogue
// grid (NX/128, NCPAD/128)
// =====================================================================
__global__ void __launch_bounds__(256, 2)
nca_mma_kernel(const int* __restrict__ cy)
{
    extern __shared__ char sm[];
    __shared__ float s_cn[128];
    __shared__ int   s_cy[128];
    __shared__ float s_xn[128];
    __shared__ __align__(16) __half s_oh[16 * 136];   // one-hot [class][cand], 272B stride
    const uint32_t sb = smem_u32(sm);
    const int tid = threadIdx.x, wid = tid >> 5, lane = tid & 31;
    const int mw = wid >> 1, nw = wid & 1;
    const int xBase = blockIdx.x * 128;
    const int cBase = blockIdx.y * 128;

    // prologue: fold norm8 reduction; poison padded cands (exp -> 0)
    if (tid < 128) {
        const int j = cBase + tid;
        const float* p = g_nrm8 + (size_t)j * 8;
        const float s = ((p[0] + p[1]) + (p[2] + p[3])) + ((p[4] + p[5]) + (p[6] + p[7]));
        s_cn[tid] = (j < NC) ? s : 1e30f;
        s_cy[tid] = cy[min(j, NC - 1)];
    } else {
        const int r = NCPAD + xBase + (tid - 128);
        const float* p = g_nrm8 + (size_t)r * 8;
        s_xn[tid - 128] = ((p[0] + p[1]) + (p[2] + p[3])) + ((p[4] + p[5]) + (p[6] + p[7]));
    }

    const char* gA = (const char*)(g_emb + (size_t)(NCPAD + xBase) * DIM);
    const char* gB = (const char*)(g_emb + (size_t)cBase * DIM);

    float acc[16][4];
#pragma unroll
    for (int t = 0; t < 16; t++)
#pragma unroll
        for (int u = 0; u < 4; u++) acc[t][u] = 0.f;

    gemm_main(sb, gA, gB, DIM * 2, 8, acc, mw, nw, lane, tid);

    __syncthreads();   // ring buffers no longer read; reuse as P tile

    // build one-hot tile (classes 10..15 stay zero-padded)
    if (tid < 128) {
        const int y = s_cy[tid];
#pragma unroll
        for (int c = 0; c < 16; c++)
            s_oh[c * 136 + tid] = (y == c) ? __float2half(1.f) : __float2half(0.f);
    }

    // scores -> e = exp(-dist) -> fp16 P tile (scores <= 0, no max needed)
    const int g = lane >> 2, tig = lane & 3;
    float xnr[4];
#pragma unroll
    for (int i = 0; i < 4; i++) xnr[i] = s_xn[mw * 32 + 8 * i + g];
#pragma unroll
    for (int t = 0; t < 16; t++) {
        const int rhalf = t >> 3;
        const int col = nw * 64 + (t & 7) * 8 + tig * 2;
        const float cn0 = s_cn[col], cn1 = s_cn[col + 1];
        float e[4];
#pragma unroll
        for (int u = 0; u < 4; u++) {
            const float xn = xnr[rhalf * 2 + (u >> 1)];
            const float cn = (u & 1) ? cn1 : cn0;
            const float sq = fmaxf(xn + cn - 2.f * acc[t][u], 1e-12f);
            float d;
            asm("sqrt.approx.f32 %0, %1;" : "=f"(d) : "f"(sq));
            e[u] = __expf(-d);
        }
        const int row0 = mw * 32 + rhalf * 16 + g;
        *(uint32_t*)(sm + row0 * PSTR + col * 2)       = h2pack(e[0], e[1]);
        *(uint32_t*)(sm + (row0 + 8) * PSTR + col * 2) = h2pack(e[2], e[3]);
    }
    __syncthreads();

    // class GEMM: D[128 rows x 16 classes] = P(128x128) @ onehot^T, fp32 accum
    float d0[4] = {0.f, 0.f, 0.f, 0.f};
    float d1[4] = {0.f, 0.f, 0.f, 0.f};
    const uint32_t arow = sb + (uint32_t)(wid * 16 + (lane & 15)) * PSTR
                        + ((uint32_t)(lane >> 4)) * 16;
    const uint32_t ohb  = smem_u32(s_oh) + (uint32_t)(lane & 7) * PSTR
                        + ((uint32_t)((lane >> 3) & 1)) * 16;
#pragma unroll
    for (int ks = 0; ks < 8; ks++) {
        uint32_t a4[4];
        ldsm4(a4[0], a4[1], a4[2], a4[3], arow + ks * 32);
        uint32_t b0[2], b1[2];
        ldsm2(b0[0], b0[1], ohb + ks * 32);
        ldsm2(b1[0], b1[1], ohb + 8 * PSTR + ks * 32);
        mma16816(d0, a4, b0);
        mma16816(d1, a4, b1);
    }
    {
        float* P0 = g_part + ((size_t)(xBase + wid * 16 + g) * NSPLIT + blockIdx.y) * D_OUT;
        float* P1 = g_part + ((size_t)(xBase + wid * 16 + 8 + g) * NSPLIT + blockIdx.y) * D_OUT;
        P0[tig * 2]     = d0[0];
        P0[tig * 2 + 1] = d0[1];
        P1[tig * 2]     = d0[2];
        P1[tig * 2 + 1] = d0[3];
        if (tig == 0) {
            P0[8] = d1[0]; P0[9] = d1[1];
            P1[8] = d1[2]; P1[9] = d1[3];
        }
    }
}

// =====================================================================
// Kernel 5: reduce partials -> log-probs (warp per x row, deterministic)
// =====================================================================
__global__ void __launch_bounds__(256)
finalize_kernel(float* __restrict__ out)
{
    const int w = (blockIdx.x * 256 + threadIdx.x) >> 5;
    const int lane = threadIdx.x & 31;
    if (w >= NX) return;
    const float* P = g_part + (size_t)w * NSPLIT * D_OUT;
    float n[D_OUT];
#pragma unroll
    for (int c = 0; c < D_OUT; c++) n[c] = 0.f;
    for (int s = lane; s < NSPLIT; s += 32) {
        const float* q = P + s * D_OUT;
#pragma unroll
        for (int c = 0; c < D_OUT; c++) n[c] += q[c];
    }
#pragma unroll
    for (int o = 16; o; o >>= 1)
#pragma unroll
        for (int c = 0; c < D_OUT; c++) n[c] += __shfl_xor_sync(0xffffffffu, n[c], o);
    if (lane == 0) {
        float l = 0.f;
#pragma unroll
        for (int c = 0; c < D_OUT; c++) l += n[c];
        const float inv = 1.0f / l;
#pragma unroll
        for (int c = 0; c < D_OUT; c++)
            out[w * D_OUT + c] = logf(n[c] * inv + 1e-7f);
    }
}

// =====================================================================
extern "C" void kernel_launch(void* const* d_in, const int* in_sizes, int n_in,
                              void* d_out, int out_size)
{
    const float* x     = (const float*)d_in[0];
    const float* cx    = (const float*)d_in[1];
    const int*   cy    = (const int*)d_in[2];
    const float* freq  = (const float*)d_in[3];
    const float* plr_w = (const float*)d_in[4];
    const float* plr_b = (const float*)d_in[5];
    const float* enc_w = (const float*)d_in[6];
    const float* enc_b = (const float*)d_in[7];
    float* out = (float*)d_out;

    cudaFuncSetAttribute(enc_mma_kernel, cudaFuncAttributeMaxDynamicSharedMemorySize, DYNSMEM);
    cudaFuncSetAttribute(nca_mma_kernel, cudaFuncAttributeMaxDynamicSharedMemorySize, DYNSMEM);

    featgen_kernel<<<NROWS / 256, 256>>>(cx, x, freq, plr_w, plr_b);
    wprep_kernel<<<(DIM * KF + 255) / 256, 256>>>(enc_w);
    enc_mma_kernel<<<dim3(NROWS / 128, DIM / 128), 256, DYNSMEM>>>(enc_b);
    nca_mma_kernel<<<dim3(NX / 128, NCPAD / 128), 256, DYNSMEM>>>(cy);
    finalize_kernel<<<(NX * 32) / 256, 256>>>(out);
}

// round 14
// speedup vs baseline: 1.6745x; 1.1803x over previous
#include <cuda_runtime.h>
#include <cuda_fp16.h>
#include <stdint.h>
#include <math.h>

#define D_IN     32
#define KF       832            // padded feature dim (13*64)
#define DIM      512
#define D_OUT    10
#define NX       1024
#define NC       100000
#define NCPAD    102400         // 800 * 128
#define NROWS    (NCPAD + NX)   // 103424 = 808*128
#define NSPLIT   800            // candidate blocks of 128
#define TWO_PI   6.283185307179586f

// stage geometry: K-chunk 64 halves (128B) per tile row, 144B padded stride
#define ROWSTR   144
#define TILEB    (128 * ROWSTR)     // 18432
#define STAGEB   (2 * TILEB)        // 36864 (A + B)
#define NSTAGE   2
#define DYNSMEM  (NSTAGE * STAGEB)  // 73728 -> 2 CTAs/SM by smem

// P tile (exp scores) reuses the ring: 128 rows x 272B stride
#define PSTR     272

// ---------------- device scratch (alloc-free) ----------------
__device__ __align__(16) __half g_fb[(size_t)NROWS * KF];   // fp16 feats
__device__ __align__(16) __half g_wb[(size_t)DIM * KF];     // fp16 enc_w
__device__ __align__(16) __half g_emb[(size_t)NROWS * DIM]; // fp16 embeddings
__device__ float g_nrm8[(size_t)NROWS * 8];                 // per-(128col x nwarp) partial norms
__device__ float g_part[(size_t)NX * NSPLIT * D_OUT];

// ---------------- PTX helpers (base-sm_103 legal) ----------------
__device__ __forceinline__ uint32_t smem_u32(const void* p) {
    uint32_t a;
    asm("{ .reg .u64 t; cvta.to.shared.u64 t, %1; cvt.u32.u64 %0, t; }" : "=r"(a) : "l"(p));
    return a;
}
__device__ __forceinline__ void ldsm4(uint32_t& r0, uint32_t& r1, uint32_t& r2, uint32_t& r3, uint32_t a) {
    asm volatile("ldmatrix.sync.aligned.m8n8.x4.shared.b16 {%0,%1,%2,%3}, [%4];"
                 : "=r"(r0), "=r"(r1), "=r"(r2), "=r"(r3) : "r"(a));
}
__device__ __forceinline__ void ldsm2(uint32_t& r0, uint32_t& r1, uint32_t a) {
    asm volatile("ldmatrix.sync.aligned.m8n8.x2.shared.b16 {%0,%1}, [%2];"
                 : "=r"(r0), "=r"(r1) : "r"(a));
}
__device__ __forceinline__ void mma16816(float* c, const uint32_t* a, const uint32_t* b) {
    asm volatile("mma.sync.aligned.m16n8k16.row.col.f32.f16.f16.f32 "
                 "{%0,%1,%2,%3}, {%4,%5,%6,%7}, {%8,%9}, {%0,%1,%2,%3};"
                 : "+f"(c[0]), "+f"(c[1]), "+f"(c[2]), "+f"(c[3])
                 : "r"(a[0]), "r"(a[1]), "r"(a[2]), "r"(a[3]), "r"(b[0]), "r"(b[1]));
}
__device__ __forceinline__ void cp16(uint32_t dst, const void* src) {
    asm volatile("cp.async.cg.shared.global [%0], [%1], 16;" :: "r"(dst), "l"(src));
}
#define CP_COMMIT() asm volatile("cp.async.commit_group;" ::: "memory")
#define CP_WAIT0()  asm volatile("cp.async.wait_group 0;" ::: "memory")

__device__ __forceinline__ uint32_t h2pack(float a, float b) {
    __half2 h = __floats2half2_rn(a, b);
    return *(uint32_t*)&h;
}

// fast sincos on the FMA pipe (abs err < 3e-8)
__device__ __forceinline__ void fsincos(float z, float* s, float* c) {
    const float t  = z * 0.6366197723675814f;
    const float qm = t + 12582912.0f;
    const float q  = qm - 12582912.0f;
    const int   iq = (int)__float_as_uint(qm) & 3;
    float r = fmaf(q, -1.57079637e+00f, z);
    r = fmaf(q, 4.3711388e-08f, r);
    const float r2 = r * r;
    float ps = fmaf(r2, fmaf(r2, fmaf(r2, fmaf(r2, 2.7557319e-6f, -1.9841270e-4f),
                    8.3333333e-3f), -1.6666667e-1f), 1.0f) * r;
    float pc = fmaf(r2, fmaf(r2, fmaf(r2, fmaf(r2, 2.4801587e-5f, -1.3888889e-3f),
                    4.1666667e-2f), -5.0e-1f), 1.0f);
    float ss = (iq & 1) ? pc : ps;
    float cc = (iq & 1) ? ps : pc;
    if (iq & 2) ss = -ss;
    if ((iq + 1) & 2) cc = -cc;
    *s = ss; *c = cc;
}

// stage one 128-row x 128-byte chunk for A and B: 2048 cp16 / 256 thr = 8 each
__device__ __forceinline__ void stageAB(uint32_t sbase, const char* gA, const char* gB,
                                        int str, int tid)
{
#pragma unroll
    for (int it = 0; it < 8; it++) {
        const int e   = it * 256 + tid;
        const int isB = e >> 10;
        const int id  = e & 1023;
        const int r   = id >> 3;
        const int s   = id & 7;
        const char* g = isB ? gB : gA;
        cp16(sbase + isB * TILEB + r * ROWSTR + s * 16, g + (size_t)r * str + s * 16);
    }
}

// warp microkernel: m32 x n64 (4m x 2n warp grid) over one 64-wide K chunk
__device__ __forceinline__ void gemm_step(uint32_t sbuf, float (*acc)[4],
                                          int mw, int nw, int lane)
{
    const uint32_t a0 = sbuf + (uint32_t)(mw * 32 + (lane & 15)) * ROWSTR
                      + ((uint32_t)(lane >> 4) & 1) * 16;
    const uint32_t a1 = a0 + 16 * ROWSTR;
    const uint32_t b0 = sbuf + TILEB
                      + (uint32_t)(nw * 64 + (lane & 7) + ((lane >> 4) << 3)) * ROWSTR
                      + ((uint32_t)(lane >> 3) & 1) * 16;
#pragma unroll
    for (int ks = 0; ks < 4; ks++) {
        const uint32_t kc = ks * 32;
        uint32_t ah0[4], ah1[4];
        ldsm4(ah0[0], ah0[1], ah0[2], ah0[3], a0 + kc);
        ldsm4(ah1[0], ah1[1], ah1[2], ah1[3], a1 + kc);
        uint32_t bh[16];
#pragma unroll
        for (int p = 0; p < 4; p++)
            ldsm4(bh[4*p], bh[4*p+1], bh[4*p+2], bh[4*p+3], b0 + kc + p * (16 * ROWSTR));
#pragma unroll
        for (int t = 0; t < 8; t++) {
            mma16816(acc[t],     ah0, &bh[2*t]);
            mma16816(acc[8 + t], ah1, &bh[2*t]);
        }
    }
}

// 2-stage, single-sync pipelined mainloop (K advances 128B per iter).
__device__ __forceinline__ void gemm_main(uint32_t sb, const char* gA, const char* gB,
                                          int str, int niter, float (*acc)[4],
                                          int mw, int nw, int lane, int tid)
{
    stageAB(sb, gA, gB, str, tid); CP_COMMIT();
    uint32_t bufs[2] = { sb, sb + STAGEB };
    for (int kb = 0; kb < niter; kb++) {
        CP_WAIT0();
        __syncthreads();
        if (kb + 1 < niter) {
            stageAB(bufs[(kb + 1) & 1], gA + (kb + 1) * 128, gB + (kb + 1) * 128, str, tid);
            CP_COMMIT();
        }
        gemm_step(bufs[kb & 1], acc, mw, nw, lane);
    }
}

// =====================================================================
// Kernel 1: feature generation -> fp16 rows via tensor-core PLR MLP.
// 128 rows/block, 8 warps x 16 rows. Sincos computed DIRECTLY into mma
// A-fragment layout (thread (g,tig): rows {g,g+8}, freqs {2tig,2tig+1,
// 2tig+8,2tig+9} -> 256 (row,f) pairs per warp, no duplication).
// =====================================================================
__global__ void __launch_bounds__(256)
featgen_kernel(const float* __restrict__ cx, const float* __restrict__ xx,
               const float* __restrict__ freq, const float* __restrict__ plr_w,
               const float* __restrict__ plr_b)
{
    __shared__ float s_x[128 * 33];
    __shared__ float s_fr[384];
    const int tid = threadIdx.x, wid = tid >> 5, lane = tid & 31;
    const int g = lane >> 2, tig = lane & 3;
    const size_t rowBase = (size_t)blockIdx.x * 128;

    for (int i = tid; i < 384; i += 256) s_fr[i] = TWO_PI * freq[i];
    for (int i = tid; i < 128 * 32; i += 256) {
        const int r = i >> 5, k = i & 31;
        const size_t gr = rowBase + r;
        float v = 0.f;
        if (gr < NC) v = cx[gr * D_IN + k];
        else if (gr >= NCPAD) v = xx[(gr - NCPAD) * D_IN + k];
        s_x[r * 33 + k] = v;
    }

    // B fragments (plr_w^T) + bias, loaded once per thread from gmem
    uint32_t bcos[4][2], bsin[4][2];
    float pb[8];
#pragma unroll
    for (int nt = 0; nt < 4; nt++) {
        const float* W = plr_w + (nt * 8 + g) * 32;
        bcos[nt][0] = h2pack(W[tig * 2],      W[tig * 2 + 1]);
        bcos[nt][1] = h2pack(W[tig * 2 + 8],  W[tig * 2 + 9]);
        bsin[nt][0] = h2pack(W[16 + tig * 2], W[16 + tig * 2 + 1]);
        bsin[nt][1] = h2pack(W[24 + tig * 2], W[24 + tig * 2 + 1]);
        pb[nt * 2]     = plr_b[nt * 8 + tig * 2];
        pb[nt * 2 + 1] = plr_b[nt * 8 + tig * 2 + 1];
    }
    __syncthreads();

    const int r0 = wid * 16 + g, r1 = r0 + 8;
    __half* dst0 = g_fb + (rowBase + r0) * KF;
    __half* dst1 = g_fb + (rowBase + r1) * KF;

    for (int n = 0; n < 24; n++) {
        const float x0 = s_x[r0 * 33 + n], x1 = s_x[r1 * 33 + n];
        float c0[4], s0[4], c1[4], s1[4];
#pragma unroll
        for (int j = 0; j < 4; j++) {
            const int f = tig * 2 + ((j < 2) ? j : (6 + j));   // 2t,2t+1,2t+8,2t+9
            const float fr = s_fr[n * 16 + f];
            fsincos(fr * x0, &s0[j], &c0[j]);
            fsincos(fr * x1, &s1[j], &c1[j]);
        }
        const uint32_t ac[4] = { h2pack(c0[0], c0[1]), h2pack(c1[0], c1[1]),
                                 h2pack(c0[2], c0[3]), h2pack(c1[2], c1[3]) };
        const uint32_t as[4] = { h2pack(s0[0], s0[1]), h2pack(s1[0], s1[1]),
                                 h2pack(s0[2], s0[3]), h2pack(s1[2], s1[3]) };
#pragma unroll
        for (int nt = 0; nt < 4; nt++) {
            float c[4] = {0.f, 0.f, 0.f, 0.f};
            mma16816(c, ac, bcos[nt]);
            mma16816(c, as, bsin[nt]);
            const float b0 = pb[nt * 2], b1 = pb[nt * 2 + 1];
            const int col = n * 32 + nt * 8 + tig * 2;
            *(uint32_t*)(dst0 + col) = h2pack(fmaxf(c[0] + b0, 0.f), fmaxf(c[1] + b1, 0.f));
            *(uint32_t*)(dst1 + col) = h2pack(fmaxf(c[2] + b0, 0.f), fmaxf(c[3] + b1, 0.f));
        }
    }
    // cat tail 768..775 + zero pad to 832
    if (tid < 128) {
        __half* dst = g_fb + (rowBase + tid) * KF;
#pragma unroll 8
        for (int k = 0; k < 64; k++)
            dst[768 + k] = __float2half_rn((k < 8) ? s_x[tid * 33 + 24 + k] : 0.f);
    }
}

// =====================================================================
// Kernel 2: pack enc_w -> fp16
// =====================================================================
__global__ void wprep_kernel(const float* __restrict__ enc_w)
{
    const int idx = blockIdx.x * 256 + threadIdx.x;
    if (idx >= DIM * KF) return;
    const int n = idx / KF, k = idx % KF;
    g_wb[(size_t)n * KF + k] = __float2half_rn((k < 776) ? enc_w[n * 776 + k] : 0.f);
}

// =====================================================================
// Kernel 3: encode GEMM (128 rows x 128 cols), fused partial norms
// grid (DIM/128, NROWS/128): colBase FASTEST so the 4 consumers of each
// A row-block run concurrently -> A read once into L2 (not 4x from DRAM)
// =====================================================================
__global__ void __launch_bounds__(256, 2)
enc_mma_kernel(const float* __restrict__ enc_b)
{
    extern __shared__ char sm[];
    __shared__ float s_bias[128];
    const uint32_t sb = smem_u32(sm);
    const int tid = threadIdx.x, wid = tid >> 5, lane = tid & 31;
    const int mw = wid >> 1, nw = wid & 1;
    const size_t rowBase = (size_t)blockIdx.y * 128;
    const int colBase = blockIdx.x * 128;
    if (tid < 128) s_bias[tid] = enc_b[colBase + tid];

    const char* gA = (const char*)(g_fb + rowBase * KF);
    const char* gB = (const char*)(g_wb + (size_t)colBase * KF);

    float acc[16][4];
#pragma unroll
    for (int t = 0; t < 16; t++)
#pragma unroll
        for (int u = 0; u < 4; u++) acc[t][u] = 0.f;

    gemm_main(sb, gA, gB, KF * 2, 13, acc, mw, nw, lane, tid);

    // epilogue: bias, fp16 store, quad-reduced partial norms (4 rows/thread)
    const int g = lane >> 2, tig = lane & 3;
    const int nslot = blockIdx.x * 2 + nw;      // 0..7
    float nrm[4] = {0.f, 0.f, 0.f, 0.f};
#pragma unroll
    for (int t = 0; t < 8; t++) {
        const int bcol = nw * 64 + t * 8 + tig * 2;
        const int col = colBase + bcol;
        const float b0 = s_bias[bcol], b1 = s_bias[bcol + 1];
        const float v00 = acc[t][0] + b0,     v01 = acc[t][1] + b1;
        const float v02 = acc[t][2] + b0,     v03 = acc[t][3] + b1;
        const float v10 = acc[8 + t][0] + b0, v11 = acc[8 + t][1] + b1;
        const float v12 = acc[8 + t][2] + b0, v13 = acc[8 + t][3] + b1;
        const size_t r = rowBase + mw * 32 + g;
        *(uint32_t*)(g_emb + r * DIM + col)        = h2pack(v00, v01);
        *(uint32_t*)(g_emb + (r + 8) * DIM + col)  = h2pack(v02, v03);
        *(uint32_t*)(g_emb + (r + 16) * DIM + col) = h2pack(v10, v11);
        *(uint32_t*)(g_emb + (r + 24) * DIM + col) = h2pack(v12, v13);
        nrm[0] = fmaf(v00, v00, fmaf(v01, v01, nrm[0]));
        nrm[1] = fmaf(v02, v02, fmaf(v03, v03, nrm[1]));
        nrm[2] = fmaf(v10, v10, fmaf(v11, v11, nrm[2]));
        nrm[3] = fmaf(v12, v12, fmaf(v13, v13, nrm[3]));
    }
#pragma unroll
    for (int i = 0; i < 4; i++) {
        nrm[i] += __shfl_xor_sync(0xffffffffu, nrm[i], 1);
        nrm[i] += __shfl_xor_sync(0xffffffffu, nrm[i], 2);
    }
    if (tig == 0) {
        const size_t r = rowBase + mw * 32 + g;
        g_nrm8[r * 8 + nslot]        = nrm[0];
        g_nrm8[(r + 8) * 8 + nslot]  = nrm[1];
        g_nrm8[(r + 16) * 8 + nslot] = nrm[2];
        g_nrm8[(r + 24) * 8 + nslot] = nrm[3];
    }
}

// =====================================================================
// Kernel 4: NCA GEMM + exp + one-hot class MMA epilogue
// grid (NX/128, NCPAD/128)
// =====================================================================
__global__ void __launch_bounds__(256, 2)
nca_mma_kernel(const int* __restrict__ cy)
{
    extern __shared__ char sm[];
    __shared__ float s_cn[128];
    __shared__ int   s_cy[128];
    __shared__ float s_xn[128];
    __shared__ __align__(16) __half s_oh[16 * 136];   // one-hot [class][cand], 272B stride
    const uint32_t sb = smem_u32(sm);
    const int tid = threadIdx.x, wid = tid >> 5, lane = tid & 31;
    const int mw = wid >> 1, nw = wid & 1;
    const int xBase = blockIdx.x * 128;
    const int cBase = blockIdx.y * 128;

    // prologue: fold norm8 reduction; poison padded cands (exp -> 0)
    if (tid < 128) {
        const int j = cBase + tid;
        const float* p = g_nrm8 + (size_t)j * 8;
        const float s = ((p[0] + p[1]) + (p[2] + p[3])) + ((p[4] + p[5]) + (p[6] + p[7]));
        s_cn[tid] = (j < NC) ? s : 1e30f;
        s_cy[tid] = cy[min(j, NC - 1)];
    } else {
        const int r = NCPAD + xBase + (tid - 128);
        const float* p = g_nrm8 + (size_t)r * 8;
        s_xn[tid - 128] = ((p[0] + p[1]) + (p[2] + p[3])) + ((p[4] + p[5]) + (p[6] + p[7]));
    }

    const char* gA = (const char*)(g_emb + (size_t)(NCPAD + xBase) * DIM);
    const char* gB = (const char*)(g_emb + (size_t)cBase * DIM);

    float acc[16][4];
#pragma unroll
    for (int t = 0; t < 16; t++)
#pragma unroll
        for (int u = 0; u < 4; u++) acc[t][u] = 0.f;

    gemm_main(sb, gA, gB, DIM * 2, 8, acc, mw, nw, lane, tid);

    __syncthreads();   // ring buffers no longer read; reuse as P tile

    // build one-hot tile (classes 10..15 stay zero-padded)
    if (tid < 128) {
        const int y = s_cy[tid];
#pragma unroll
        for (int c = 0; c < 16; c++)
            s_oh[c * 136 + tid] = (y == c) ? __float2half(1.f) : __float2half(0.f);
    }

    // scores -> e = exp(-dist) -> fp16 P tile (scores <= 0, no max needed)
    const int g = lane >> 2, tig = lane & 3;
    float xnr[4];
#pragma unroll
    for (int i = 0; i < 4; i++) xnr[i] = s_xn[mw * 32 + 8 * i + g];
#pragma unroll
    for (int t = 0; t < 16; t++) {
        const int rhalf = t >> 3;
        const int col = nw * 64 + (t & 7) * 8 + tig * 2;
        const float cn0 = s_cn[col], cn1 = s_cn[col + 1];
        float e[4];
#pragma unroll
        for (int u = 0; u < 4; u++) {
            const float xn = xnr[rhalf * 2 + (u >> 1)];
            const float cn = (u & 1) ? cn1 : cn0;
            const float sq = fmaxf(xn + cn - 2.f * acc[t][u], 1e-12f);
            float d;
            asm("sqrt.approx.f32 %0, %1;" : "=f"(d) : "f"(sq));
            e[u] = __expf(-d);
        }
        const int row0 = mw * 32 + rhalf * 16 + g;
        *(uint32_t*)(sm + row0 * PSTR + col * 2)       = h2pack(e[0], e[1]);
        *(uint32_t*)(sm + (row0 + 8) * PSTR + col * 2) = h2pack(e[2], e[3]);
    }
    __syncthreads();

    // class GEMM: D[128 rows x 16 classes] = P(128x128) @ onehot^T, fp32 accum
    float d0[4] = {0.f, 0.f, 0.f, 0.f};
    float d1[4] = {0.f, 0.f, 0.f, 0.f};
    const uint32_t arow = sb + (uint32_t)(wid * 16 + (lane & 15)) * PSTR
                        + ((uint32_t)(lane >> 4)) * 16;
    const uint32_t ohb  = smem_u32(s_oh) + (uint32_t)(lane & 7) * PSTR
                        + ((uint32_t)((lane >> 3) & 1)) * 16;
#pragma unroll
    for (int ks = 0; ks < 8; ks++) {
        uint32_t a4[4];
        ldsm4(a4[0], a4[1], a4[2], a4[3], arow + ks * 32);
        uint32_t b0[2], b1[2];
        ldsm2(b0[0], b0[1], ohb + ks * 32);
        ldsm2(b1[0], b1[1], ohb + 8 * PSTR + ks * 32);
        mma16816(d0, a4, b0);
        mma16816(d1, a4, b1);
    }
    {
        float* P0 = g_part + ((size_t)(xBase + wid * 16 + g) * NSPLIT + blockIdx.y) * D_OUT;
        float* P1 = g_part + ((size_t)(xBase + wid * 16 + 8 + g) * NSPLIT + blockIdx.y) * D_OUT;
        P0[tig * 2]     = d0[0];
        P0[tig * 2 + 1] = d0[1];
        P1[tig * 2]     = d0[2];
        P1[tig * 2 + 1] = d0[3];
        if (tig == 0) {
            P0[8] = d1[0]; P0[9] = d1[1];
            P1[8] = d1[2]; P1[9] = d1[3];
        }
    }
}

// =====================================================================
// Kernel 5: reduce partials -> log-probs (warp per x row, deterministic)
// =====================================================================
__global__ void __launch_bounds__(256)
finalize_kernel(float* __restrict__ out)
{
    const int w = (blockIdx.x * 256 + threadIdx.x) >> 5;
    const int lane = threadIdx.x & 31;
    if (w >= NX) return;
    const float* P = g_part + (size_t)w * NSPLIT * D_OUT;
    float n[D_OUT];
#pragma unroll
    for (int c = 0; c < D_OUT; c++) n[c] = 0.f;
    for (int s = lane; s < NSPLIT; s += 32) {
        const float* q = P + s * D_OUT;
#pragma unroll
        for (int c = 0; c < D_OUT; c++) n[c] += q[c];
    }
#pragma unroll
    for (int o = 16; o; o >>= 1)
#pragma unroll
        for (int c = 0; c < D_OUT; c++) n[c] += __shfl_xor_sync(0xffffffffu, n[c], o);
    if (lane == 0) {
        float l = 0.f;
#pragma unroll
        for (int c = 0; c < D_OUT; c++) l += n[c];
        const float inv = 1.0f / l;
#pragma unroll
        for (int c = 0; c < D_OUT; c++)
            out[w * D_OUT + c] = logf(n[c] * inv + 1e-7f);
    }
}

// =====================================================================
extern "C" void kernel_launch(void* const* d_in, const int* in_sizes, int n_in,
                              void* d_out, int out_size)
{
    const float* x     = (const float*)d_in[0];
    const float* cx    = (const float*)d_in[1];
    const int*   cy    = (const int*)d_in[2];
    const float* freq  = (const float*)d_in[3];
    const float* plr_w = (const float*)d_in[4];
    const float* plr_b = (const float*)d_in[5];
    const float* enc_w = (const float*)d_in[6];
    const float* enc_b = (const float*)d_in[7];
    float* out = (float*)d_out;

    cudaFuncSetAttribute(enc_mma_kernel, cudaFuncAttributeMaxDynamicSharedMemorySize, DYNSMEM);
    cudaFuncSetAttribute(nca_mma_kernel, cudaFuncAttributeMaxDynamicSharedMemorySize, DYNSMEM);

    featgen_kernel<<<NROWS / 128, 256>>>(cx, x, freq, plr_w, plr_b);
    wprep_kernel<<<(DIM * KF + 255) / 256, 256>>>(enc_w);
    enc_mma_kernel<<<dim3(DIM / 128, NROWS / 128), 256, DYNSMEM>>>(enc_b);
    nca_mma_kernel<<<dim3(NX / 128, NCPAD / 128), 256, DYNSMEM>>>(cy);
    finalize_kernel<<<(NX * 32) / 256, 256>>>(out);
}

// round 15
// speedup vs baseline: 1.6861x; 1.0069x over previous
#include <cuda_runtime.h>
#include <cuda_fp16.h>
#include <stdint.h>
#include <math.h>

#define D_IN     32
#define KF       832            // padded feature dim (13*64)
#define DIM      512
#define D_OUT    10
#define NX       1024
#define NC       100000
#define NCPAD    102400         // 800 * 128
#define NROWS    (NCPAD + NX)   // 103424 = 808*128
#define NSPLIT   800            // candidate blocks of 128
#define TWO_PI   6.283185307179586f

// stage geometry: K-chunk 64 halves (128B) per tile row, 144B padded stride
#define ROWSTR   144
#define TILEB    (128 * ROWSTR)     // 18432
#define STAGEB   (2 * TILEB)        // 36864 (A + B)
#define NSTAGE   2
#define DYNSMEM  (NSTAGE * STAGEB)  // 73728 -> 2 CTAs/SM by smem

// P tile (exp scores) reuses the ring: 128 rows x 272B stride
#define PSTR     272

// ---------------- device scratch (alloc-free) ----------------
__device__ __align__(16) __half g_fb[(size_t)NROWS * KF];   // fp16 feats
__device__ __align__(16) __half g_wb[(size_t)DIM * KF];     // fp16 enc_w
__device__ __align__(16) __half g_emb[(size_t)NROWS * DIM]; // fp16 embeddings
__device__ float g_nrm8[(size_t)NROWS * 8];                 // per-(128col x nwarp) partial norms
__device__ float g_part[(size_t)NX * NSPLIT * D_OUT];

// ---------------- PTX helpers (base-sm_103 legal) ----------------
__device__ __forceinline__ uint32_t smem_u32(const void* p) {
    uint32_t a;
    asm("{ .reg .u64 t; cvta.to.shared.u64 t, %1; cvt.u32.u64 %0, t; }" : "=r"(a) : "l"(p));
    return a;
}
__device__ __forceinline__ void ldsm4(uint32_t& r0, uint32_t& r1, uint32_t& r2, uint32_t& r3, uint32_t a) {
    asm volatile("ldmatrix.sync.aligned.m8n8.x4.shared.b16 {%0,%1,%2,%3}, [%4];"
                 : "=r"(r0), "=r"(r1), "=r"(r2), "=r"(r3) : "r"(a));
}
__device__ __forceinline__ void ldsm2(uint32_t& r0, uint32_t& r1, uint32_t a) {
    asm volatile("ldmatrix.sync.aligned.m8n8.x2.shared.b16 {%0,%1}, [%2];"
                 : "=r"(r0), "=r"(r1) : "r"(a));
}
__device__ __forceinline__ void mma16816(float* c, const uint32_t* a, const uint32_t* b) {
    asm volatile("mma.sync.aligned.m16n8k16.row.col.f32.f16.f16.f32 "
                 "{%0,%1,%2,%3}, {%4,%5,%6,%7}, {%8,%9}, {%0,%1,%2,%3};"
                 : "+f"(c[0]), "+f"(c[1]), "+f"(c[2]), "+f"(c[3])
                 : "r"(a[0]), "r"(a[1]), "r"(a[2]), "r"(a[3]), "r"(b[0]), "r"(b[1]));
}
__device__ __forceinline__ void cp16(uint32_t dst, const void* src) {
    asm volatile("cp.async.cg.shared.global [%0], [%1], 16;" :: "r"(dst), "l"(src));
}
#define CP_COMMIT() asm volatile("cp.async.commit_group;" ::: "memory")
#define CP_WAIT0()  asm volatile("cp.async.wait_group 0;" ::: "memory")

__device__ __forceinline__ uint32_t h2pack(float a, float b) {
    __half2 h = __floats2half2_rn(a, b);
    return *(uint32_t*)&h;
}
// {lo=a, hi=b} packed conversion (PTX operand order: first source -> high half)
__device__ __forceinline__ uint32_t cvt_f16x2(float lo, float hi) {
    uint32_t r;
    asm("cvt.rn.f16x2.f32 %0, %1, %2;" : "=r"(r) : "f"(hi), "f"(lo));
    return r;
}
__device__ __forceinline__ uint32_t ex2_f16x2(uint32_t a) {
    uint32_t r;
    asm("ex2.approx.f16x2 %0, %1;" : "=r"(r) : "r"(a));
    return r;
}
__device__ __forceinline__ uint32_t mul_f16x2(uint32_t a, uint32_t b) {
    uint32_t r;
    asm("mul.f16x2 %0, %1, %2;" : "=r"(r) : "r"(a), "r"(b));
    return r;
}

// fast sincos on the FMA pipe (abs err < 3e-8)
__device__ __forceinline__ void fsincos(float z, float* s, float* c) {
    const float t  = z * 0.6366197723675814f;
    const float qm = t + 12582912.0f;
    const float q  = qm - 12582912.0f;
    const int   iq = (int)__float_as_uint(qm) & 3;
    float r = fmaf(q, -1.57079637e+00f, z);
    r = fmaf(q, 4.3711388e-08f, r);
    const float r2 = r * r;
    float ps = fmaf(r2, fmaf(r2, fmaf(r2, fmaf(r2, 2.7557319e-6f, -1.9841270e-4f),
                    8.3333333e-3f), -1.6666667e-1f), 1.0f) * r;
    float pc = fmaf(r2, fmaf(r2, fmaf(r2, fmaf(r2, 2.4801587e-5f, -1.3888889e-3f),
                    4.1666667e-2f), -5.0e-1f), 1.0f);
    float ss = (iq & 1) ? pc : ps;
    float cc = (iq & 1) ? ps : pc;
    if (iq & 2) ss = -ss;
    if ((iq + 1) & 2) cc = -cc;
    *s = ss; *c = cc;
}

// stage one 128-row x 128-byte chunk for A and B: 2048 cp16 / 256 thr = 8 each
__device__ __forceinline__ void stageAB(uint32_t sbase, const char* gA, const char* gB,
                                        int str, int tid)
{
#pragma unroll
    for (int it = 0; it < 8; it++) {
        const int e   = it * 256 + tid;
        const int isB = e >> 10;
        const int id  = e & 1023;
        const int r   = id >> 3;
        const int s   = id & 7;
        const char* g = isB ? gB : gA;
        cp16(sbase + isB * TILEB + r * ROWSTR + s * 16, g + (size_t)r * str + s * 16);
    }
}

// warp microkernel: m32 x n64 (4m x 2n warp grid) over one 64-wide K chunk
__device__ __forceinline__ void gemm_step(uint32_t sbuf, float (*acc)[4],
                                          int mw, int nw, int lane)
{
    const uint32_t a0 = sbuf + (uint32_t)(mw * 32 + (lane & 15)) * ROWSTR
                      + ((uint32_t)(lane >> 4) & 1) * 16;
    const uint32_t a1 = a0 + 16 * ROWSTR;
    const uint32_t b0 = sbuf + TILEB
                      + (uint32_t)(nw * 64 + (lane & 7) + ((lane >> 4) << 3)) * ROWSTR
                      + ((uint32_t)(lane >> 3) & 1) * 16;
#pragma unroll
    for (int ks = 0; ks < 4; ks++) {
        const uint32_t kc = ks * 32;
        uint32_t ah0[4], ah1[4];
        ldsm4(ah0[0], ah0[1], ah0[2], ah0[3], a0 + kc);
        ldsm4(ah1[0], ah1[1], ah1[2], ah1[3], a1 + kc);
        uint32_t bh[16];
#pragma unroll
        for (int p = 0; p < 4; p++)
            ldsm4(bh[4*p], bh[4*p+1], bh[4*p+2], bh[4*p+3], b0 + kc + p * (16 * ROWSTR));
#pragma unroll
        for (int t = 0; t < 8; t++) {
            mma16816(acc[t],     ah0, &bh[2*t]);
            mma16816(acc[8 + t], ah1, &bh[2*t]);
        }
    }
}

// 2-stage, single-sync pipelined mainloop (K advances 128B per iter).
__device__ __forceinline__ void gemm_main(uint32_t sb, const char* gA, const char* gB,
                                          int str, int niter, float (*acc)[4],
                                          int mw, int nw, int lane, int tid)
{
    stageAB(sb, gA, gB, str, tid); CP_COMMIT();
    uint32_t bufs[2] = { sb, sb + STAGEB };
    for (int kb = 0; kb < niter; kb++) {
        CP_WAIT0();
        __syncthreads();
        if (kb + 1 < niter) {
            stageAB(bufs[(kb + 1) & 1], gA + (kb + 1) * 128, gB + (kb + 1) * 128, str, tid);
            CP_COMMIT();
        }
        gemm_step(bufs[kb & 1], acc, mw, nw, lane);
    }
}

// =====================================================================
// Kernel 1: feature generation -> fp16 rows via tensor-core PLR MLP
// =====================================================================
__global__ void __launch_bounds__(256)
featgen_kernel(const float* __restrict__ cx, const float* __restrict__ xx,
               const float* __restrict__ freq, const float* __restrict__ plr_w,
               const float* __restrict__ plr_b)
{
    __shared__ float s_x[128 * 33];
    __shared__ float s_fr[384];
    const int tid = threadIdx.x, wid = tid >> 5, lane = tid & 31;
    const int g = lane >> 2, tig = lane & 3;
    const size_t rowBase = (size_t)blockIdx.x * 128;

    for (int i = tid; i < 384; i += 256) s_fr[i] = TWO_PI * freq[i];
    for (int i = tid; i < 128 * 32; i += 256) {
        const int r = i >> 5, k = i & 31;
        const size_t gr = rowBase + r;
        float v = 0.f;
        if (gr < NC) v = cx[gr * D_IN + k];
        else if (gr >= NCPAD) v = xx[(gr - NCPAD) * D_IN + k];
        s_x[r * 33 + k] = v;
    }

    uint32_t bcos[4][2], bsin[4][2];
    float pb[8];
#pragma unroll
    for (int nt = 0; nt < 4; nt++) {
        const float* W = plr_w + (nt * 8 + g) * 32;
        bcos[nt][0] = h2pack(W[tig * 2],      W[tig * 2 + 1]);
        bcos[nt][1] = h2pack(W[tig * 2 + 8],  W[tig * 2 + 9]);
        bsin[nt][0] = h2pack(W[16 + tig * 2], W[16 + tig * 2 + 1]);
        bsin[nt][1] = h2pack(W[24 + tig * 2], W[24 + tig * 2 + 1]);
        pb[nt * 2]     = plr_b[nt * 8 + tig * 2];
        pb[nt * 2 + 1] = plr_b[nt * 8 + tig * 2 + 1];
    }
    __syncthreads();

    const int r0 = wid * 16 + g, r1 = r0 + 8;
    __half* dst0 = g_fb + (rowBase + r0) * KF;
    __half* dst1 = g_fb + (rowBase + r1) * KF;

    for (int n = 0; n < 24; n++) {
        const float x0 = s_x[r0 * 33 + n], x1 = s_x[r1 * 33 + n];
        float c0[4], s0[4], c1[4], s1[4];
#pragma unroll
        for (int j = 0; j < 4; j++) {
            const int f = tig * 2 + ((j < 2) ? j : (6 + j));
            const float fr = s_fr[n * 16 + f];
            fsincos(fr * x0, &s0[j], &c0[j]);
            fsincos(fr * x1, &s1[j], &c1[j]);
        }
        const uint32_t ac[4] = { h2pack(c0[0], c0[1]), h2pack(c1[0], c1[1]),
                                 h2pack(c0[2], c0[3]), h2pack(c1[2], c1[3]) };
        const uint32_t as[4] = { h2pack(s0[0], s0[1]), h2pack(s1[0], s1[1]),
                                 h2pack(s0[2], s0[3]), h2pack(s1[2], s1[3]) };
#pragma unroll
        for (int nt = 0; nt < 4; nt++) {
            float c[4] = {0.f, 0.f, 0.f, 0.f};
            mma16816(c, ac, bcos[nt]);
            mma16816(c, as, bsin[nt]);
            const float b0 = pb[nt * 2], b1 = pb[nt * 2 + 1];
            const int col = n * 32 + nt * 8 + tig * 2;
            *(uint32_t*)(dst0 + col) = h2pack(fmaxf(c[0] + b0, 0.f), fmaxf(c[1] + b1, 0.f));
            *(uint32_t*)(dst1 + col) = h2pack(fmaxf(c[2] + b0, 0.f), fmaxf(c[3] + b1, 0.f));
        }
    }
    if (tid < 128) {
        __half* dst = g_fb + (rowBase + tid) * KF;
#pragma unroll 8
        for (int k = 0; k < 64; k++)
            dst[768 + k] = __float2half_rn((k < 8) ? s_x[tid * 33 + 24 + k] : 0.f);
    }
}

// =====================================================================
// Kernel 2: pack enc_w -> fp16
// =====================================================================
__global__ void wprep_kernel(const float* __restrict__ enc_w)
{
    const int idx = blockIdx.x * 256 + threadIdx.x;
    if (idx >= DIM * KF) return;
    const int n = idx / KF, k = idx % KF;
    g_wb[(size_t)n * KF + k] = __float2half_rn((k < 776) ? enc_w[n * 776 + k] : 0.f);
}

// =====================================================================
// Kernel 3: encode GEMM (128 rows x 128 cols), fused partial norms
// grid (DIM/128, NROWS/128): colBase fastest -> A read once into L2
// =====================================================================
__global__ void __launch_bounds__(256, 2)
enc_mma_kernel(const float* __restrict__ enc_b)
{
    extern __shared__ char sm[];
    __shared__ float s_bias[128];
    const uint32_t sb = smem_u32(sm);
    const int tid = threadIdx.x, wid = tid >> 5, lane = tid & 31;
    const int mw = wid >> 1, nw = wid & 1;
    const size_t rowBase = (size_t)blockIdx.y * 128;
    const int colBase = blockIdx.x * 128;
    if (tid < 128) s_bias[tid] = enc_b[colBase + tid];

    const char* gA = (const char*)(g_fb + rowBase * KF);
    const char* gB = (const char*)(g_wb + (size_t)colBase * KF);

    float acc[16][4];
#pragma unroll
    for (int t = 0; t < 16; t++)
#pragma unroll
        for (int u = 0; u < 4; u++) acc[t][u] = 0.f;

    gemm_main(sb, gA, gB, KF * 2, 13, acc, mw, nw, lane, tid);

    const int g = lane >> 2, tig = lane & 3;
    const int nslot = blockIdx.x * 2 + nw;
    float nrm[4] = {0.f, 0.f, 0.f, 0.f};
#pragma unroll
    for (int t = 0; t < 8; t++) {
        const int bcol = nw * 64 + t * 8 + tig * 2;
        const int col = colBase + bcol;
        const float b0 = s_bias[bcol], b1 = s_bias[bcol + 1];
        const float v00 = acc[t][0] + b0,     v01 = acc[t][1] + b1;
        const float v02 = acc[t][2] + b0,     v03 = acc[t][3] + b1;
        const float v10 = acc[8 + t][0] + b0, v11 = acc[8 + t][1] + b1;
        const float v12 = acc[8 + t][2] + b0, v13 = acc[8 + t][3] + b1;
        const size_t r = rowBase + mw * 32 + g;
        *(uint32_t*)(g_emb + r * DIM + col)        = h2pack(v00, v01);
        *(uint32_t*)(g_emb + (r + 8) * DIM + col)  = h2pack(v02, v03);
        *(uint32_t*)(g_emb + (r + 16) * DIM + col) = h2pack(v10, v11);
        *(uint32_t*)(g_emb + (r + 24) * DIM + col) = h2pack(v12, v13);
        nrm[0] = fmaf(v00, v00, fmaf(v01, v01, nrm[0]));
        nrm[1] = fmaf(v02, v02, fmaf(v03, v03, nrm[1]));
        nrm[2] = fmaf(v10, v10, fmaf(v11, v11, nrm[2]));
        nrm[3] = fmaf(v12, v12, fmaf(v13, v13, nrm[3]));
    }
#pragma unroll
    for (int i = 0; i < 4; i++) {
        nrm[i] += __shfl_xor_sync(0xffffffffu, nrm[i], 1);
        nrm[i] += __shfl_xor_sync(0xffffffffu, nrm[i], 2);
    }
    if (tig == 0) {
        const size_t r = rowBase + mw * 32 + g;
        g_nrm8[r * 8 + nslot]        = nrm[0];
        g_nrm8[(r + 8) * 8 + nslot]  = nrm[1];
        g_nrm8[(r + 16) * 8 + nslot] = nrm[2];
        g_nrm8[(r + 24) * 8 + nslot] = nrm[3];
    }
}

// =====================================================================
// Kernel 4: NCA GEMM + half2-exp + permuted one-hot class MMA epilogue.
// P columns permuted (new = tig*16 + t*2 + u) so stores are STS.128;
// one-hot built with the same permutation -> identical contraction.
// =====================================================================
__global__ void __launch_bounds__(256, 2)
nca_mma_kernel(const int* __restrict__ cy)
{
    extern __shared__ char sm[];
    __shared__ float s_cn[128];
    __shared__ int   s_cy[128];
    __shared__ float s_xn[128];
    __shared__ __align__(16) __half s_oh[16 * 136];
    const uint32_t sb = smem_u32(sm);
    const int tid = threadIdx.x, wid = tid >> 5, lane = tid & 31;
    const int mw = wid >> 1, nw = wid & 1;
    const int xBase = blockIdx.x * 128;
    const int cBase = blockIdx.y * 128;

    if (tid < 128) {
        const int j = cBase + tid;
        const float* p = g_nrm8 + (size_t)j * 8;
        const float s = ((p[0] + p[1]) + (p[2] + p[3])) + ((p[4] + p[5]) + (p[6] + p[7]));
        s_cn[tid] = (j < NC) ? s : 1e30f;
        s_cy[tid] = cy[min(j, NC - 1)];
    } else {
        const int r = NCPAD + xBase + (tid - 128);
        const float* p = g_nrm8 + (size_t)r * 8;
        s_xn[tid - 128] = ((p[0] + p[1]) + (p[2] + p[3])) + ((p[4] + p[5]) + (p[6] + p[7]));
    }

    const char* gA = (const char*)(g_emb + (size_t)(NCPAD + xBase) * DIM);
    const char* gB = (const char*)(g_emb + (size_t)cBase * DIM);

    float acc[16][4];
#pragma unroll
    for (int t = 0; t < 16; t++)
#pragma unroll
        for (int u = 0; u < 4; u++) acc[t][u] = 0.f;

    gemm_main(sb, gA, gB, DIM * 2, 8, acc, mw, nw, lane, tid);

    __syncthreads();   // ring buffers no longer read; reuse as P tile

    // one-hot with the SAME candidate permutation as the P store:
    // new position tid -> old col half*64 + tg*2 + tt*8 + uu
    if (tid < 128) {
        const int half = tid >> 6, nu = tid & 63;
        const int tg = nu >> 4, tt = (nu >> 1) & 7, uu = nu & 1;
        const int y = s_cy[half * 64 + tg * 2 + tt * 8 + uu];
#pragma unroll
        for (int c = 0; c < 16; c++)
            s_oh[c * 136 + tid] = (y == c) ? __float2half(1.f) : __float2half(0.f);
    }

    // scores -> e = exp(-d) in half2 (scores <= 0, no max needed).
    // per thread: 4 rows x 8 half2, contiguous 32B runs -> 2 STS.128/row
    const int g = lane >> 2, tig = lane & 3;
    const uint32_t nl2e = h2pack(-1.4426950408889634f, -1.4426950408889634f);
    float xnr[4];
#pragma unroll
    for (int i = 0; i < 4; i++) xnr[i] = s_xn[mw * 32 + 8 * i + g];
#pragma unroll
    for (int r = 0; r < 4; r++) {
        const float xn = xnr[r];
        const int tb = (r >> 1) * 8;      // acc base: m-frag
        const int ub = (r & 1) * 2;       // u base within acc
        uint32_t pout[8];
#pragma unroll
        for (int t = 0; t < 8; t++) {
            const int colb = nw * 64 + t * 8 + tig * 2;
            const float sq0 = fmaxf(xn + s_cn[colb]     - 2.f * acc[tb + t][ub],     1e-12f);
            const float sq1 = fmaxf(xn + s_cn[colb + 1] - 2.f * acc[tb + t][ub + 1], 1e-12f);
            float d0, d1;
            asm("sqrt.approx.f32 %0, %1;" : "=f"(d0) : "f"(sq0));
            asm("sqrt.approx.f32 %0, %1;" : "=f"(d1) : "f"(sq1));
            pout[t] = ex2_f16x2(mul_f16x2(cvt_f16x2(d0, d1), nl2e));
        }
        char* dst = sm + (mw * 32 + r * 8 + g) * PSTR + nw * 128 + tig * 32;
        *(uint4*)dst        = make_uint4(pout[0], pout[1], pout[2], pout[3]);
        *(uint4*)(dst + 16) = make_uint4(pout[4], pout[5], pout[6], pout[7]);
    }
    __syncthreads();

    // class GEMM: D[128 rows x 16 classes] = P(128x128) @ onehot^T, fp32 accum
    float d0[4] = {0.f, 0.f, 0.f, 0.f};
    float d1[4] = {0.f, 0.f, 0.f, 0.f};
    const uint32_t arow = sb + (uint32_t)(wid * 16 + (lane & 15)) * PSTR
                        + ((uint32_t)(lane >> 4)) * 16;
    const uint32_t ohb  = smem_u32(s_oh) + (uint32_t)(lane & 7) * PSTR
                        + ((uint32_t)((lane >> 3) & 1)) * 16;
#pragma unroll
    for (int ks = 0; ks < 8; ks++) {
        uint32_t a4[4];
        ldsm4(a4[0], a4[1], a4[2], a4[3], arow + ks * 32);
        uint32_t b0[2], b1[2];
        ldsm2(b0[0], b0[1], ohb + ks * 32);
        ldsm2(b1[0], b1[1], ohb + 8 * PSTR + ks * 32);
        mma16816(d0, a4, b0);
        mma16816(d1, a4, b1);
    }
    {
        const int tg = lane & 3;
        float* P0 = g_part + ((size_t)(xBase + wid * 16 + g) * NSPLIT + blockIdx.y) * D_OUT;
        float* P1 = g_part + ((size_t)(xBase + wid * 16 + 8 + g) * NSPLIT + blockIdx.y) * D_OUT;
        P0[tg * 2]     = d0[0];
        P0[tg * 2 + 1] = d0[1];
        P1[tg * 2]     = d0[2];
        P1[tg * 2 + 1] = d0[3];
        if (tg == 0) {
            P0[8] = d1[0]; P0[9] = d1[1];
            P1[8] = d1[2]; P1[9] = d1[3];
        }
    }
}

// =====================================================================
// Kernel 5: reduce partials -> log-probs (warp per x row, deterministic)
// =====================================================================
__global__ void __launch_bounds__(256)
finalize_kernel(float* __restrict__ out)
{
    const int w = (blockIdx.x * 256 + threadIdx.x) >> 5;
    const int lane = threadIdx.x & 31;
    if (w >= NX) return;
    const float* P = g_part + (size_t)w * NSPLIT * D_OUT;
    float n[D_OUT];
#pragma unroll
    for (int c = 0; c < D_OUT; c++) n[c] = 0.f;
    for (int s = lane; s < NSPLIT; s += 32) {
        const float* q = P + s * D_OUT;
#pragma unroll
        for (int c = 0; c < D_OUT; c++) n[c] += q[c];
    }
#pragma unroll
    for (int o = 16; o; o >>= 1)
#pragma unroll
        for (int c = 0; c < D_OUT; c++) n[c] += __shfl_xor_sync(0xffffffffu, n[c], o);
    if (lane == 0) {
        float l = 0.f;
#pragma unroll
        for (int c = 0; c < D_OUT; c++) l += n[c];
        const float inv = 1.0f / l;
#pragma unroll
        for (int c = 0; c < D_OUT; c++)
            out[w * D_OUT + c] = logf(n[c] * inv + 1e-7f);
    }
}

// =====================================================================
extern "C" void kernel_launch(void* const* d_in, const int* in_sizes, int n_in,
                              void* d_out, int out_size)
{
    const float* x     = (const float*)d_in[0];
    const float* cx    = (const float*)d_in[1];
    const int*   cy    = (const int*)d_in[2];
    const float* freq  = (const float*)d_in[3];
    const float* plr_w = (const float*)d_in[4];
    const float* plr_b = (const float*)d_in[5];
    const float* enc_w = (const float*)d_in[6];
    const float* enc_b = (const float*)d_in[7];
    float* out = (float*)d_out;

    cudaFuncSetAttribute(enc_mma_kernel, cudaFuncAttributeMaxDynamicSharedMemorySize, DYNSMEM);
    cudaFuncSetAttribute(nca_mma_kernel, cudaFuncAttributeMaxDynamicSharedMemorySize, DYNSMEM);

    featgen_kernel<<<NROWS / 128, 256>>>(cx, x, freq, plr_w, plr_b);
    wprep_kernel<<<(DIM * KF + 255) / 256, 256>>>(enc_w);
    enc_mma_kernel<<<dim3(DIM / 128, NROWS / 128), 256, DYNSMEM>>>(enc_b);
    nca_mma_kernel<<<dim3(NX / 128, NCPAD / 128), 256, DYNSMEM>>>(cy);
    finalize_kernel<<<(NX * 32) / 256, 256>>>(out);
}

// round 16
// speedup vs baseline: 1.7207x; 1.0205x over previous
#include <cuda_runtime.h>
#include <cuda_fp16.h>
#include <stdint.h>
#include <math.h>

#define D_IN     32
#define KF       832            // padded feature dim (13*64)
#define DIM      512
#define D_OUT    10
#define NX       1024
#define NC       100000
#define NCPAD    102400         // 800 * 128
#define NROWS    (NCPAD + NX)   // 103424 = 808*128
#define NSPLIT   800            // candidate blocks of 128
#define TWO_PI   6.283185307179586f

// stage geometry: K-chunk 64 halves (128B) per tile row, 144B padded stride
#define ROWSTR   144
#define TILEB    (128 * ROWSTR)     // 18432
#define STAGEB   (2 * TILEB)        // 36864 (A + B)
#define NSTAGE   2
#define DYNSMEM  (NSTAGE * STAGEB)  // 73728 -> 2 CTAs/SM by smem

// P tile (exp scores) reuses the ring: 128 rows x 272B stride
#define PSTR     272

// ---------------- device scratch (alloc-free) ----------------
__device__ __align__(16) __half g_fb[(size_t)NROWS * KF];   // fp16 feats
__device__ __align__(16) __half g_wb[(size_t)DIM * KF];     // fp16 enc_w
__device__ __align__(16) __half g_emb[(size_t)NROWS * DIM]; // fp16 embeddings
__device__ float g_nrm8[(size_t)NROWS * 8];                 // per-(128col x nwarp) partial norms
__device__ float g_part[(size_t)NX * NSPLIT * D_OUT];

// ---------------- PTX helpers (base-sm_103 legal) ----------------
__device__ __forceinline__ uint32_t smem_u32(const void* p) {
    uint32_t a;
    asm("{ .reg .u64 t; cvta.to.shared.u64 t, %1; cvt.u32.u64 %0, t; }" : "=r"(a) : "l"(p));
    return a;
}
__device__ __forceinline__ void ldsm4(uint32_t& r0, uint32_t& r1, uint32_t& r2, uint32_t& r3, uint32_t a) {
    asm volatile("ldmatrix.sync.aligned.m8n8.x4.shared.b16 {%0,%1,%2,%3}, [%4];"
                 : "=r"(r0), "=r"(r1), "=r"(r2), "=r"(r3) : "r"(a));
}
__device__ __forceinline__ void ldsm2(uint32_t& r0, uint32_t& r1, uint32_t a) {
    asm volatile("ldmatrix.sync.aligned.m8n8.x2.shared.b16 {%0,%1}, [%2];"
                 : "=r"(r0), "=r"(r1) : "r"(a));
}
__device__ __forceinline__ void mma16816(float* c, const uint32_t* a, const uint32_t* b) {
    asm volatile("mma.sync.aligned.m16n8k16.row.col.f32.f16.f16.f32 "
                 "{%0,%1,%2,%3}, {%4,%5,%6,%7}, {%8,%9}, {%0,%1,%2,%3};"
                 : "+f"(c[0]), "+f"(c[1]), "+f"(c[2]), "+f"(c[3])
                 : "r"(a[0]), "r"(a[1]), "r"(a[2]), "r"(a[3]), "r"(b[0]), "r"(b[1]));
}
__device__ __forceinline__ void cp16(uint32_t dst, const void* src) {
    asm volatile("cp.async.cg.shared.global [%0], [%1], 16;" :: "r"(dst), "l"(src));
}
#define CP_COMMIT() asm volatile("cp.async.commit_group;" ::: "memory")
#define CP_WAIT0()  asm volatile("cp.async.wait_group 0;" ::: "memory")

__device__ __forceinline__ uint32_t h2pack(float a, float b) {
    __half2 h = __floats2half2_rn(a, b);
    return *(uint32_t*)&h;
}
// {lo=a, hi=b} packed conversion (PTX operand order: first source -> high half)
__device__ __forceinline__ uint32_t cvt_f16x2(float lo, float hi) {
    uint32_t r;
    asm("cvt.rn.f16x2.f32 %0, %1, %2;" : "=r"(r) : "f"(hi), "f"(lo));
    return r;
}
__device__ __forceinline__ uint32_t ex2_f16x2(uint32_t a) {
    uint32_t r;
    asm("ex2.approx.f16x2 %0, %1;" : "=r"(r) : "r"(a));
    return r;
}
__device__ __forceinline__ uint32_t mul_f16x2(uint32_t a, uint32_t b) {
    uint32_t r;
    asm("mul.f16x2 %0, %1, %2;" : "=r"(r) : "r"(a), "r"(b));
    return r;
}

// fast sincos on the FMA pipe (abs err < 3e-8)
__device__ __forceinline__ void fsincos(float z, float* s, float* c) {
    const float t  = z * 0.6366197723675814f;
    const float qm = t + 12582912.0f;
    const float q  = qm - 12582912.0f;
    const int   iq = (int)__float_as_uint(qm) & 3;
    float r = fmaf(q, -1.57079637e+00f, z);
    r = fmaf(q, 4.3711388e-08f, r);
    const float r2 = r * r;
    float ps = fmaf(r2, fmaf(r2, fmaf(r2, fmaf(r2, 2.7557319e-6f, -1.9841270e-4f),
                    8.3333333e-3f), -1.6666667e-1f), 1.0f) * r;
    float pc = fmaf(r2, fmaf(r2, fmaf(r2, fmaf(r2, 2.4801587e-5f, -1.3888889e-3f),
                    4.1666667e-2f), -5.0e-1f), 1.0f);
    float ss = (iq & 1) ? pc : ps;
    float cc = (iq & 1) ? ps : pc;
    if (iq & 2) ss = -ss;
    if ((iq + 1) & 2) cc = -cc;
    *s = ss; *c = cc;
}

// stage one 128-row x 128-byte chunk for A and B: 2048 cp16 / 256 thr = 8 each
__device__ __forceinline__ void stageAB(uint32_t sbase, const char* gA, const char* gB,
                                        int str, int tid)
{
#pragma unroll
    for (int it = 0; it < 8; it++) {
        const int e   = it * 256 + tid;
        const int isB = e >> 10;
        const int id  = e & 1023;
        const int r   = id >> 3;
        const int s   = id & 7;
        const char* g = isB ? gB : gA;
        cp16(sbase + isB * TILEB + r * ROWSTR + s * 16, g + (size_t)r * str + s * 16);
    }
}

// warp microkernel: m32 x n64 (4m x 2n warp grid) over one 64-wide K chunk.
// k-steps are rotated per warp (ks = (kss + wid) & 3) to break the post-barrier
// phase alignment: at any instant some warps on an SMSP issue MMAs while others
// are in their LDSM burst, keeping the tensor pipe fed. Valid because the full
// chunk is resident in smem and fp32 accumulation tolerates k-step reordering.
__device__ __forceinline__ void gemm_step(uint32_t sbuf, float (*acc)[4],
                                          int mw, int nw, int wid, int lane)
{
    const uint32_t a0 = sbuf + (uint32_t)(mw * 32 + (lane & 15)) * ROWSTR
                      + ((uint32_t)(lane >> 4) & 1) * 16;
    const uint32_t a1 = a0 + 16 * ROWSTR;
    const uint32_t b0 = sbuf + TILEB
                      + (uint32_t)(nw * 64 + (lane & 7) + ((lane >> 4) << 3)) * ROWSTR
                      + ((uint32_t)(lane >> 3) & 1) * 16;
#pragma unroll
    for (int kss = 0; kss < 4; kss++) {
        const uint32_t kc = (uint32_t)(((kss + wid) & 3) * 32);
        uint32_t ah0[4], ah1[4];
        ldsm4(ah0[0], ah0[1], ah0[2], ah0[3], a0 + kc);
        ldsm4(ah1[0], ah1[1], ah1[2], ah1[3], a1 + kc);
        uint32_t bh[16];
#pragma unroll
        for (int p = 0; p < 4; p++)
            ldsm4(bh[4*p], bh[4*p+1], bh[4*p+2], bh[4*p+3], b0 + kc + p * (16 * ROWSTR));
#pragma unroll
        for (int t = 0; t < 8; t++) {
            mma16816(acc[t],     ah0, &bh[2*t]);
            mma16816(acc[8 + t], ah1, &bh[2*t]);
        }
    }
}

// 2-stage, single-sync pipelined mainloop (K advances 128B per iter).
__device__ __forceinline__ void gemm_main(uint32_t sb, const char* gA, const char* gB,
                                          int str, int niter, float (*acc)[4],
                                          int mw, int nw, int wid, int lane, int tid)
{
    stageAB(sb, gA, gB, str, tid); CP_COMMIT();
    uint32_t bufs[2] = { sb, sb + STAGEB };
    for (int kb = 0; kb < niter; kb++) {
        CP_WAIT0();
        __syncthreads();
        if (kb + 1 < niter) {
            stageAB(bufs[(kb + 1) & 1], gA + (kb + 1) * 128, gB + (kb + 1) * 128, str, tid);
            CP_COMMIT();
        }
        gemm_step(bufs[kb & 1], acc, mw, nw, wid, lane);
    }
}

// =====================================================================
// Kernel 1: feature generation -> fp16 rows via tensor-core PLR MLP
// =====================================================================
__global__ void __launch_bounds__(256)
featgen_kernel(const float* __restrict__ cx, const float* __restrict__ xx,
               const float* __restrict__ freq, const float* __restrict__ plr_w,
               const float* __restrict__ plr_b)
{
    __shared__ float s_x[128 * 33];
    __shared__ float s_fr[384];
    const int tid = threadIdx.x, wid = tid >> 5, lane = tid & 31;
    const int g = lane >> 2, tig = lane & 3;
    const size_t rowBase = (size_t)blockIdx.x * 128;

    for (int i = tid; i < 384; i += 256) s_fr[i] = TWO_PI * freq[i];
    for (int i = tid; i < 128 * 32; i += 256) {
        const int r = i >> 5, k = i & 31;
        const size_t gr = rowBase + r;
        float v = 0.f;
        if (gr < NC) v = cx[gr * D_IN + k];
        else if (gr >= NCPAD) v = xx[(gr - NCPAD) * D_IN + k];
        s_x[r * 33 + k] = v;
    }

    uint32_t bcos[4][2], bsin[4][2];
    float pb[8];
#pragma unroll
    for (int nt = 0; nt < 4; nt++) {
        const float* W = plr_w + (nt * 8 + g) * 32;
        bcos[nt][0] = h2pack(W[tig * 2],      W[tig * 2 + 1]);
        bcos[nt][1] = h2pack(W[tig * 2 + 8],  W[tig * 2 + 9]);
        bsin[nt][0] = h2pack(W[16 + tig * 2], W[16 + tig * 2 + 1]);
        bsin[nt][1] = h2pack(W[24 + tig * 2], W[24 + tig * 2 + 1]);
        pb[nt * 2]     = plr_b[nt * 8 + tig * 2];
        pb[nt * 2 + 1] = plr_b[nt * 8 + tig * 2 + 1];
    }
    __syncthreads();

    const int r0 = wid * 16 + g, r1 = r0 + 8;
    __half* dst0 = g_fb + (rowBase + r0) * KF;
    __half* dst1 = g_fb + (rowBase + r1) * KF;

    for (int n = 0; n < 24; n++) {
        const float x0 = s_x[r0 * 33 + n], x1 = s_x[r1 * 33 + n];
        float c0[4], s0[4], c1[4], s1[4];
#pragma unroll
        for (int j = 0; j < 4; j++) {
            const int f = tig * 2 + ((j < 2) ? j : (6 + j));
            const float fr = s_fr[n * 16 + f];
            fsincos(fr * x0, &s0[j], &c0[j]);
            fsincos(fr * x1, &s1[j], &c1[j]);
        }
        const uint32_t ac[4] = { h2pack(c0[0], c0[1]), h2pack(c1[0], c1[1]),
                                 h2pack(c0[2], c0[3]), h2pack(c1[2], c1[3]) };
        const uint32_t as[4] = { h2pack(s0[0], s0[1]), h2pack(s1[0], s1[1]),
                                 h2pack(s0[2], s0[3]), h2pack(s1[2], s1[3]) };
#pragma unroll
        for (int nt = 0; nt < 4; nt++) {
            float c[4] = {0.f, 0.f, 0.f, 0.f};
            mma16816(c, ac, bcos[nt]);
            mma16816(c, as, bsin[nt]);
            const float b0 = pb[nt * 2], b1 = pb[nt * 2 + 1];
            const int col = n * 32 + nt * 8 + tig * 2;
            *(uint32_t*)(dst0 + col) = h2pack(fmaxf(c[0] + b0, 0.f), fmaxf(c[1] + b1, 0.f));
            *(uint32_t*)(dst1 + col) = h2pack(fmaxf(c[2] + b0, 0.f), fmaxf(c[3] + b1, 0.f));
        }
    }
    if (tid < 128) {
        __half* dst = g_fb + (rowBase + tid) * KF;
        uint32_t tail[4];
#pragma unroll
        for (int q = 0; q < 4; q++)
            tail[q] = h2pack(s_x[tid * 33 + 24 + q * 2], s_x[tid * 33 + 24 + q * 2 + 1]);
        *(uint4*)(dst + 768) = make_uint4(tail[0], tail[1], tail[2], tail[3]);
        const uint4 z = make_uint4(0u, 0u, 0u, 0u);
#pragma unroll
        for (int q = 1; q < 8; q++) *(uint4*)(dst + 768 + q * 8) = z;
    }
}

// =====================================================================
// Kernel 2: pack enc_w -> fp16
// =====================================================================
__global__ void wprep_kernel(const float* __restrict__ enc_w)
{
    const int idx = blockIdx.x * 256 + threadIdx.x;
    if (idx >= DIM * KF) return;
    const int n = idx / KF, k = idx % KF;
    g_wb[(size_t)n * KF + k] = __float2half_rn((k < 776) ? enc_w[n * 776 + k] : 0.f);
}

// =====================================================================
// Kernel 3: encode GEMM (128 rows x 128 cols), fused partial norms
// grid (DIM/128, NROWS/128): colBase fastest -> A read once into L2
// =====================================================================
__global__ void __launch_bounds__(256, 2)
enc_mma_kernel(const float* __restrict__ enc_b)
{
    extern __shared__ char sm[];
    __shared__ float s_bias[128];
    const uint32_t sb = smem_u32(sm);
    const int tid = threadIdx.x, wid = tid >> 5, lane = tid & 31;
    const int mw = wid >> 1, nw = wid & 1;
    const size_t rowBase = (size_t)blockIdx.y * 128;
    const int colBase = blockIdx.x * 128;
    if (tid < 128) s_bias[tid] = enc_b[colBase + tid];

    const char* gA = (const char*)(g_fb + rowBase * KF);
    const char* gB = (const char*)(g_wb + (size_t)colBase * KF);

    float acc[16][4];
#pragma unroll
    for (int t = 0; t < 16; t++)
#pragma unroll
        for (int u = 0; u < 4; u++) acc[t][u] = 0.f;

    gemm_main(sb, gA, gB, KF * 2, 13, acc, mw, nw, wid, lane, tid);

    const int g = lane >> 2, tig = lane & 3;
    const int nslot = blockIdx.x * 2 + nw;
    float nrm[4] = {0.f, 0.f, 0.f, 0.f};
#pragma unroll
    for (int t = 0; t < 8; t++) {
        const int bcol = nw * 64 + t * 8 + tig * 2;
        const int col = colBase + bcol;
        const float b0 = s_bias[bcol], b1 = s_bias[bcol + 1];
        const float v00 = acc[t][0] + b0,     v01 = acc[t][1] + b1;
        const float v02 = acc[t][2] + b0,     v03 = acc[t][3] + b1;
        const float v10 = acc[8 + t][0] + b0, v11 = acc[8 + t][1] + b1;
        const float v12 = acc[8 + t][2] + b0, v13 = acc[8 + t][3] + b1;
        const size_t r = rowBase + mw * 32 + g;
        *(uint32_t*)(g_emb + r * DIM + col)        = h2pack(v00, v01);
        *(uint32_t*)(g_emb + (r + 8) * DIM + col)  = h2pack(v02, v03);
        *(uint32_t*)(g_emb + (r + 16) * DIM + col) = h2pack(v10, v11);
        *(uint32_t*)(g_emb + (r + 24) * DIM + col) = h2pack(v12, v13);
        nrm[0] = fmaf(v00, v00, fmaf(v01, v01, nrm[0]));
        nrm[1] = fmaf(v02, v02, fmaf(v03, v03, nrm[1]));
        nrm[2] = fmaf(v10, v10, fmaf(v11, v11, nrm[2]));
        nrm[3] = fmaf(v12, v12, fmaf(v13, v13, nrm[3]));
    }
#pragma unroll
    for (int i = 0; i < 4; i++) {
        nrm[i] += __shfl_xor_sync(0xffffffffu, nrm[i], 1);
        nrm[i] += __shfl_xor_sync(0xffffffffu, nrm[i], 2);
    }
    if (tig == 0) {
        const size_t r = rowBase + mw * 32 + g;
        g_nrm8[r * 8 + nslot]        = nrm[0];
        g_nrm8[(r + 8) * 8 + nslot]  = nrm[1];
        g_nrm8[(r + 16) * 8 + nslot] = nrm[2];
        g_nrm8[(r + 24) * 8 + nslot] = nrm[3];
    }
}

// =====================================================================
// Kernel 4: NCA GEMM + half2-exp + permuted one-hot class MMA epilogue
// =====================================================================
__global__ void __launch_bounds__(256, 2)
nca_mma_kernel(const int* __restrict__ cy)
{
    extern __shared__ char sm[];
    __shared__ float s_cn[128];
    __shared__ int   s_cy[128];
    __shared__ float s_xn[128];
    __shared__ __align__(16) __half s_oh[16 * 136];
    const uint32_t sb = smem_u32(sm);
    const int tid = threadIdx.x, wid = tid >> 5, lane = tid & 31;
    const int mw = wid >> 1, nw = wid & 1;
    const int xBase = blockIdx.x * 128;
    const int cBase = blockIdx.y * 128;

    if (tid < 128) {
        const int j = cBase + tid;
        const float* p = g_nrm8 + (size_t)j * 8;
        const float s = ((p[0] + p[1]) + (p[2] + p[3])) + ((p[4] + p[5]) + (p[6] + p[7]));
        s_cn[tid] = (j < NC) ? s : 1e30f;
        s_cy[tid] = cy[min(j, NC - 1)];
    } else {
        const int r = NCPAD + xBase + (tid - 128);
        const float* p = g_nrm8 + (size_t)r * 8;
        s_xn[tid - 128] = ((p[0] + p[1]) + (p[2] + p[3])) + ((p[4] + p[5]) + (p[6] + p[7]));
    }

    const char* gA = (const char*)(g_emb + (size_t)(NCPAD + xBase) * DIM);
    const char* gB = (const char*)(g_emb + (size_t)cBase * DIM);

    float acc[16][4];
#pragma unroll
    for (int t = 0; t < 16; t++)
#pragma unroll
        for (int u = 0; u < 4; u++) acc[t][u] = 0.f;

    gemm_main(sb, gA, gB, DIM * 2, 8, acc, mw, nw, wid, lane, tid);

    __syncthreads();   // ring buffers no longer read; reuse as P tile

    // one-hot with the SAME candidate permutation as the P store:
    if (tid < 128) {
        const int half = tid >> 6, nu = tid & 63;
        const int tg = nu >> 4, tt = (nu >> 1) & 7, uu = nu & 1;
        const int y = s_cy[half * 64 + tg * 2 + tt * 8 + uu];
#pragma unroll
        for (int c = 0; c < 16; c++)
            s_oh[c * 136 + tid] = (y == c) ? __float2half(1.f) : __float2half(0.f);
    }

    // scores -> e = exp(-d) in half2 (scores <= 0, no max needed)
    const int g = lane >> 2, tig = lane & 3;
    const uint32_t nl2e = h2pack(-1.4426950408889634f, -1.4426950408889634f);
    float xnr[4];
#pragma unroll
    for (int i = 0; i < 4; i++) xnr[i] = s_xn[mw * 32 + 8 * i + g];
#pragma unroll
    for (int r = 0; r < 4; r++) {
        const float xn = xnr[r];
        const int tb = (r >> 1) * 8;
        const int ub = (r & 1) * 2;
        uint32_t pout[8];
#pragma unroll
        for (int t = 0; t < 8; t++) {
            const int colb = nw * 64 + t * 8 + tig * 2;
            const float sq0 = fmaxf(xn + s_cn[colb]     - 2.f * acc[tb + t][ub],     1e-12f);
            const float sq1 = fmaxf(xn + s_cn[colb + 1] - 2.f * acc[tb + t][ub + 1], 1e-12f);
            float d0, d1;
            asm("sqrt.approx.f32 %0, %1;" : "=f"(d0) : "f"(sq0));
            asm("sqrt.approx.f32 %0, %1;" : "=f"(d1) : "f"(sq1));
            pout[t] = ex2_f16x2(mul_f16x2(cvt_f16x2(d0, d1), nl2e));
        }
        char* dst = sm + (mw * 32 + r * 8 + g) * PSTR + nw * 128 + tig * 32;
        *(uint4*)dst        = make_uint4(pout[0], pout[1], pout[2], pout[3]);
        *(uint4*)(dst + 16) = make_uint4(pout[4], pout[5], pout[6], pout[7]);
    }
    __syncthreads();

    // class GEMM: D[128 rows x 16 classes] = P(128x128) @ onehot^T, fp32 accum
    float d0[4] = {0.f, 0.f, 0.f, 0.f};
    float d1[4] = {0.f, 0.f, 0.f, 0.f};
    const uint32_t arow = sb + (uint32_t)(wid * 16 + (lane & 15)) * PSTR
                        + ((uint32_t)(lane >> 4)) * 16;
    const uint32_t ohb  = smem_u32(s_oh) + (uint32_t)(lane & 7) * PSTR
                        + ((uint32_t)((lane >> 3) & 1)) * 16;
#pragma unroll
    for (int ks = 0; ks < 8; ks++) {
        uint32_t a4[4];
        ldsm4(a4[0], a4[1], a4[2], a4[3], arow + ks * 32);
        uint32_t b0[2], b1[2];
        ldsm2(b0[0], b0[1], ohb + ks * 32);
        ldsm2(b1[0], b1[1], ohb + 8 * PSTR + ks * 32);
        mma16816(d0, a4, b0);
        mma16816(d1, a4, b1);
    }
    {
        const int tg = lane & 3;
        float* P0 = g_part + ((size_t)(xBase + wid * 16 + g) * NSPLIT + blockIdx.y) * D_OUT;
        float* P1 = g_part + ((size_t)(xBase + wid * 16 + 8 + g) * NSPLIT + blockIdx.y) * D_OUT;
        P0[tg * 2]     = d0[0];
        P0[tg * 2 + 1] = d0[1];
        P1[tg * 2]     = d0[2];
        P1[tg * 2 + 1] = d0[3];
        if (tg == 0) {
            P0[8] = d1[0]; P0[9] = d1[1];
            P1[8] = d1[2]; P1[9] = d1[3];
        }
    }
}

// =====================================================================
// Kernel 5: reduce partials -> log-probs (warp per x row, deterministic)
// =====================================================================
__global__ void __launch_bounds__(256)
finalize_kernel(float* __restrict__ out)
{
    const int w = (blockIdx.x * 256 + threadIdx.x) >> 5;
    const int lane = threadIdx.x & 31;
    if (w >= NX) return;
    const float* P = g_part + (size_t)w * NSPLIT * D_OUT;
    float n[D_OUT];
#pragma unroll
    for (int c = 0; c < D_OUT; c++) n[c] = 0.f;
    for (int s = lane; s < NSPLIT; s += 32) {
        const float* q = P + s * D_OUT;
#pragma unroll
        for (int c = 0; c < D_OUT; c++) n[c] += q[c];
    }
#pragma unroll
    for (int o = 16; o; o >>= 1)
#pragma unroll
        for (int c = 0; c < D_OUT; c++) n[c] += __shfl_xor_sync(0xffffffffu, n[c], o);
    if (lane == 0) {
        float l = 0.f;
#pragma unroll
        for (int c = 0; c < D_OUT; c++) l += n[c];
        const float inv = 1.0f / l;
#pragma unroll
        for (int c = 0; c < D_OUT; c++)
            out[w * D_OUT + c] = logf(n[c] * inv + 1e-7f);
    }
}

// =====================================================================
extern "C" void kernel_launch(void* const* d_in, const int* in_sizes, int n_in,
                              void* d_out, int out_size)
{
    const float* x     = (const float*)d_in[0];
    const float* cx    = (const float*)d_in[1];
    const int*   cy    = (const int*)d_in[2];
    const float* freq  = (const float*)d_in[3];
    const float* plr_w = (const float*)d_in[4];
    const float* plr_b = (const float*)d_in[5];
    const float* enc_w = (const float*)d_in[6];
    const float* enc_b = (const float*)d_in[7];
    float* out = (float*)d_out;

    cudaFuncSetAttribute(enc_mma_kernel, cudaFuncAttributeMaxDynamicSharedMemorySize, DYNSMEM);
    cudaFuncSetAttribute(nca_mma_kernel, cudaFuncAttributeMaxDynamicSharedMemorySize, DYNSMEM);

    featgen_kernel<<<NROWS / 128, 256>>>(cx, x, freq, plr_w, plr_b);
    wprep_kernel<<<(DIM * KF + 255) / 256, 256>>>(enc_w);
    enc_mma_kernel<<<dim3(DIM / 128, NROWS / 128), 256, DYNSMEM>>>(enc_b);
    nca_mma_kernel<<<dim3(NX / 128, NCPAD / 128), 256, DYNSMEM>>>(cy);
    finalize_kernel<<<(NX * 32) / 256, 256>>>(out);
}

// round 17
// speedup vs baseline: 1.7599x; 1.0228x over previous
#include <cuda_runtime.h>
#include <cuda_fp16.h>
#include <stdint.h>
#include <math.h>

#define D_IN     32
#define KF       832            // padded feature dim (13*64)
#define DIM      512
#define D_OUT    10
#define NX       1024
#define NC       100000
#define NCPAD    102400         // 800 * 128
#define NROWS    (NCPAD + NX)   // 103424 = 808*128
#define NSPLIT   800            // candidate blocks of 128
#define TWO_PI   6.283185307179586f

// stage geometry: K-chunk 64 halves (128B) per tile row, 144B padded stride
#define ROWSTR   144
#define TILEB    (128 * ROWSTR)     // 18432
#define STAGEB   (2 * TILEB)        // 36864 (A + B)
#define NSTAGE   2
#define DYNSMEM  (NSTAGE * STAGEB)  // 73728 -> 2 CTAs/SM by smem

// P tile (exp scores) reuses the ring: 128 rows x 272B stride
#define PSTR     272

// ---------------- device scratch (alloc-free) ----------------
__device__ __align__(16) __half g_fb[(size_t)NROWS * KF];   // fp16 feats
__device__ __align__(16) __half g_wb[(size_t)DIM * KF];     // fp16 enc_w
__device__ __align__(16) __half g_emb[(size_t)NROWS * DIM]; // fp16 embeddings
__device__ float g_nrm8[(size_t)NROWS * 8];                 // per-(128col x nwarp) partial norms
__device__ float g_part[(size_t)NX * NSPLIT * D_OUT];

// ---------------- PTX helpers (base-sm_103 legal) ----------------
__device__ __forceinline__ uint32_t smem_u32(const void* p) {
    uint32_t a;
    asm("{ .reg .u64 t; cvta.to.shared.u64 t, %1; cvt.u32.u64 %0, t; }" : "=r"(a) : "l"(p));
    return a;
}
__device__ __forceinline__ void ldsm4(uint32_t& r0, uint32_t& r1, uint32_t& r2, uint32_t& r3, uint32_t a) {
    asm volatile("ldmatrix.sync.aligned.m8n8.x4.shared.b16 {%0,%1,%2,%3}, [%4];"
                 : "=r"(r0), "=r"(r1), "=r"(r2), "=r"(r3) : "r"(a));
}
__device__ __forceinline__ void ldsm2(uint32_t& r0, uint32_t& r1, uint32_t a) {
    asm volatile("ldmatrix.sync.aligned.m8n8.x2.shared.b16 {%0,%1}, [%2];"
                 : "=r"(r0), "=r"(r1) : "r"(a));
}
__device__ __forceinline__ void mma16816(float* c, const uint32_t* a, const uint32_t* b) {
    asm volatile("mma.sync.aligned.m16n8k16.row.col.f32.f16.f16.f32 "
                 "{%0,%1,%2,%3}, {%4,%5,%6,%7}, {%8,%9}, {%0,%1,%2,%3};"
                 : "+f"(c[0]), "+f"(c[1]), "+f"(c[2]), "+f"(c[3])
                 : "r"(a[0]), "r"(a[1]), "r"(a[2]), "r"(a[3]), "r"(b[0]), "r"(b[1]));
}
__device__ __forceinline__ void cp16(uint32_t dst, const void* src) {
    asm volatile("cp.async.cg.shared.global [%0], [%1], 16;" :: "r"(dst), "l"(src));
}
#define CP_COMMIT() asm volatile("cp.async.commit_group;" ::: "memory")
#define CP_WAIT0()  asm volatile("cp.async.wait_group 0;" ::: "memory")

__device__ __forceinline__ uint32_t h2pack(float a, float b) {
    __half2 h = __floats2half2_rn(a, b);
    return *(uint32_t*)&h;
}
// {lo=a, hi=b} packed conversion (PTX operand order: first source -> high half)
__device__ __forceinline__ uint32_t cvt_f16x2(float lo, float hi) {
    uint32_t r;
    asm("cvt.rn.f16x2.f32 %0, %1, %2;" : "=r"(r) : "f"(hi), "f"(lo));
    return r;
}
__device__ __forceinline__ uint32_t ex2_f16x2(uint32_t a) {
    uint32_t r;
    asm("ex2.approx.f16x2 %0, %1;" : "=r"(r) : "r"(a));
    return r;
}
__device__ __forceinline__ uint32_t mul_f16x2(uint32_t a, uint32_t b) {
    uint32_t r;
    asm("mul.f16x2 %0, %1, %2;" : "=r"(r) : "r"(a), "r"(b));
    return r;
}

// fast sincos on the FMA pipe (abs err < 3e-8)
__device__ __forceinline__ void fsincos(float z, float* s, float* c) {
    const float t  = z * 0.6366197723675814f;
    const float qm = t + 12582912.0f;
    const float q  = qm - 12582912.0f;
    const int   iq = (int)__float_as_uint(qm) & 3;
    float r = fmaf(q, -1.57079637e+00f, z);
    r = fmaf(q, 4.3711388e-08f, r);
    const float r2 = r * r;
    float ps = fmaf(r2, fmaf(r2, fmaf(r2, fmaf(r2, 2.7557319e-6f, -1.9841270e-4f),
                    8.3333333e-3f), -1.6666667e-1f), 1.0f) * r;
    float pc = fmaf(r2, fmaf(r2, fmaf(r2, fmaf(r2, 2.4801587e-5f, -1.3888889e-3f),
                    4.1666667e-2f), -5.0e-1f), 1.0f);
    float ss = (iq & 1) ? pc : ps;
    float cc = (iq & 1) ? ps : pc;
    if (iq & 2) ss = -ss;
    if ((iq + 1) & 2) cc = -cc;
    *s = ss; *c = cc;
}

// stage one 128-row x 128-byte chunk for A and B: 2048 cp16 / 256 thr = 8 each
__device__ __forceinline__ void stageAB(uint32_t sbase, const char* gA, const char* gB,
                                        int str, int tid)
{
#pragma unroll
    for (int it = 0; it < 8; it++) {
        const int e   = it * 256 + tid;
        const int isB = e >> 10;
        const int id  = e & 1023;
        const int r   = id >> 3;
        const int s   = id & 7;
        const char* g = isB ? gB : gA;
        cp16(sbase + isB * TILEB + r * ROWSTR + s * 16, g + (size_t)r * str + s * 16);
    }
}

// warp microkernel core (one 32-wide k-step at byte offset kc)
__device__ __forceinline__ void gemm_ks(uint32_t a0, uint32_t a1, uint32_t b0,
                                        uint32_t kc, float (*acc)[4])
{
    uint32_t ah0[4], ah1[4];
    ldsm4(ah0[0], ah0[1], ah0[2], ah0[3], a0 + kc);
    ldsm4(ah1[0], ah1[1], ah1[2], ah1[3], a1 + kc);
    uint32_t bh[16];
#pragma unroll
    for (int p = 0; p < 4; p++)
        ldsm4(bh[4*p], bh[4*p+1], bh[4*p+2], bh[4*p+3], b0 + kc + p * (16 * ROWSTR));
#pragma unroll
    for (int t = 0; t < 8; t++) {
        mma16816(acc[t],     ah0, &bh[2*t]);
        mma16816(acc[8 + t], ah1, &bh[2*t]);
    }
}

__device__ __forceinline__ void frag_bases(uint32_t sbuf, int mw, int nw, int lane,
                                           uint32_t* a0, uint32_t* a1, uint32_t* b0)
{
    *a0 = sbuf + (uint32_t)(mw * 32 + (lane & 15)) * ROWSTR
        + ((uint32_t)(lane >> 4) & 1) * 16;
    *a1 = *a0 + 16 * ROWSTR;
    *b0 = sbuf + TILEB
        + (uint32_t)(nw * 64 + (lane & 7) + ((lane >> 4) << 3)) * ROWSTR
        + ((uint32_t)(lane >> 3) & 1) * 16;
}

// ROT=1: k-steps rotated per warp (breaks post-barrier phase alignment; wins
// on the long-K enc loop). ROT=0: plain order (wins on the short nca loop).
template <int ROT>
__device__ __forceinline__ void gemm_step(uint32_t sbuf, float (*acc)[4],
                                          int mw, int nw, int wid, int lane)
{
    uint32_t a0, a1, b0;
    frag_bases(sbuf, mw, nw, lane, &a0, &a1, &b0);
#pragma unroll
    for (int kss = 0; kss < 4; kss++) {
        const uint32_t kc = ROT ? (uint32_t)(((kss + wid) & 3) * 32)
                                : (uint32_t)(kss * 32);
        gemm_ks(a0, a1, b0, kc, acc);
    }
}

// 2-stage, single-sync pipelined mainloop (K advances 128B per iter).
template <int ROT>
__device__ __forceinline__ void gemm_main(uint32_t sb, const char* gA, const char* gB,
                                          int str, int niter, float (*acc)[4],
                                          int mw, int nw, int wid, int lane, int tid)
{
    stageAB(sb, gA, gB, str, tid); CP_COMMIT();
    uint32_t bufs[2] = { sb, sb + STAGEB };
    for (int kb = 0; kb < niter; kb++) {
        CP_WAIT0();
        __syncthreads();
        if (kb + 1 < niter) {
            stageAB(bufs[(kb + 1) & 1], gA + (kb + 1) * 128, gB + (kb + 1) * 128, str, tid);
            CP_COMMIT();
        }
        gemm_step<ROT>(bufs[kb & 1], acc, mw, nw, wid, lane);
    }
}

// =====================================================================
// Kernel 1: feature generation -> fp16 rows via tensor-core PLR MLP
// =====================================================================
__global__ void __launch_bounds__(256)
featgen_kernel(const float* __restrict__ cx, const float* __restrict__ xx,
               const float* __restrict__ freq, const float* __restrict__ plr_w,
               const float* __restrict__ plr_b)
{
    __shared__ float s_x[128 * 33];
    __shared__ float s_fr[384];
    const int tid = threadIdx.x, wid = tid >> 5, lane = tid & 31;
    const int g = lane >> 2, tig = lane & 3;
    const size_t rowBase = (size_t)blockIdx.x * 128;

    for (int i = tid; i < 384; i += 256) s_fr[i] = TWO_PI * freq[i];
    for (int i = tid; i < 128 * 32; i += 256) {
        const int r = i >> 5, k = i & 31;
        const size_t gr = rowBase + r;
        float v = 0.f;
        if (gr < NC) v = cx[gr * D_IN + k];
        else if (gr >= NCPAD) v = xx[(gr - NCPAD) * D_IN + k];
        s_x[r * 33 + k] = v;
    }

    uint32_t bcos[4][2], bsin[4][2];
    float pb[8];
#pragma unroll
    for (int nt = 0; nt < 4; nt++) {
        const float* W = plr_w + (nt * 8 + g) * 32;
        bcos[nt][0] = h2pack(W[tig * 2],      W[tig * 2 + 1]);
        bcos[nt][1] = h2pack(W[tig * 2 + 8],  W[tig * 2 + 9]);
        bsin[nt][0] = h2pack(W[16 + tig * 2], W[16 + tig * 2 + 1]);
        bsin[nt][1] = h2pack(W[24 + tig * 2], W[24 + tig * 2 + 1]);
        pb[nt * 2]     = plr_b[nt * 8 + tig * 2];
        pb[nt * 2 + 1] = plr_b[nt * 8 + tig * 2 + 1];
    }
    __syncthreads();

    const int r0 = wid * 16 + g, r1 = r0 + 8;
    __half* dst0 = g_fb + (rowBase + r0) * KF;
    __half* dst1 = g_fb + (rowBase + r1) * KF;

    for (int n = 0; n < 24; n++) {
        const float x0 = s_x[r0 * 33 + n], x1 = s_x[r1 * 33 + n];
        float c0[4], s0[4], c1[4], s1[4];
#pragma unroll
        for (int j = 0; j < 4; j++) {
            const int f = tig * 2 + ((j < 2) ? j : (6 + j));
            const float fr = s_fr[n * 16 + f];
            fsincos(fr * x0, &s0[j], &c0[j]);
            fsincos(fr * x1, &s1[j], &c1[j]);
        }
        const uint32_t ac[4] = { h2pack(c0[0], c0[1]), h2pack(c1[0], c1[1]),
                                 h2pack(c0[2], c0[3]), h2pack(c1[2], c1[3]) };
        const uint32_t as[4] = { h2pack(s0[0], s0[1]), h2pack(s1[0], s1[1]),
                                 h2pack(s0[2], s0[3]), h2pack(s1[2], s1[3]) };
#pragma unroll
        for (int nt = 0; nt < 4; nt++) {
            float c[4] = {0.f, 0.f, 0.f, 0.f};
            mma16816(c, ac, bcos[nt]);
            mma16816(c, as, bsin[nt]);
            const float b0 = pb[nt * 2], b1 = pb[nt * 2 + 1];
            const int col = n * 32 + nt * 8 + tig * 2;
            *(uint32_t*)(dst0 + col) = h2pack(fmaxf(c[0] + b0, 0.f), fmaxf(c[1] + b1, 0.f));
            *(uint32_t*)(dst1 + col) = h2pack(fmaxf(c[2] + b0, 0.f), fmaxf(c[3] + b1, 0.f));
        }
    }
    if (tid < 128) {
        __half* dst = g_fb + (rowBase + tid) * KF;
        uint32_t tail[4];
#pragma unroll
        for (int q = 0; q < 4; q++)
            tail[q] = h2pack(s_x[tid * 33 + 24 + q * 2], s_x[tid * 33 + 24 + q * 2 + 1]);
        *(uint4*)(dst + 768) = make_uint4(tail[0], tail[1], tail[2], tail[3]);
        const uint4 z = make_uint4(0u, 0u, 0u, 0u);
#pragma unroll
        for (int q = 1; q < 8; q++) *(uint4*)(dst + 768 + q * 8) = z;
    }
}

// =====================================================================
// Kernel 2: pack enc_w -> fp16
// =====================================================================
__global__ void wprep_kernel(const float* __restrict__ enc_w)
{
    const int idx = blockIdx.x * 256 + threadIdx.x;
    if (idx >= DIM * KF) return;
    const int n = idx / KF, k = idx % KF;
    g_wb[(size_t)n * KF + k] = __float2half_rn((k < 776) ? enc_w[n * 776 + k] : 0.f);
}

// =====================================================================
// Kernel 3: encode GEMM (128 rows x 128 cols), fused partial norms
// grid (DIM/128, NROWS/128): colBase fastest -> A read once into L2
// =====================================================================
__global__ void __launch_bounds__(256, 2)
enc_mma_kernel(const float* __restrict__ enc_b)
{
    extern __shared__ char sm[];
    __shared__ float s_bias[128];
    const uint32_t sb = smem_u32(sm);
    const int tid = threadIdx.x, wid = tid >> 5, lane = tid & 31;
    const int mw = wid >> 1, nw = wid & 1;
    const size_t rowBase = (size_t)blockIdx.y * 128;
    const int colBase = blockIdx.x * 128;
    if (tid < 128) s_bias[tid] = enc_b[colBase + tid];

    const char* gA = (const char*)(g_fb + rowBase * KF);
    const char* gB = (const char*)(g_wb + (size_t)colBase * KF);

    float acc[16][4];
#pragma unroll
    for (int t = 0; t < 16; t++)
#pragma unroll
        for (int u = 0; u < 4; u++) acc[t][u] = 0.f;

    gemm_main<1>(sb, gA, gB, KF * 2, 13, acc, mw, nw, wid, lane, tid);

    const int g = lane >> 2, tig = lane & 3;
    const int nslot = blockIdx.x * 2 + nw;
    float nrm[4] = {0.f, 0.f, 0.f, 0.f};
#pragma unroll
    for (int t = 0; t < 8; t++) {
        const int bcol = nw * 64 + t * 8 + tig * 2;
        const int col = colBase + bcol;
        const float b0 = s_bias[bcol], b1 = s_bias[bcol + 1];
        const float v00 = acc[t][0] + b0,     v01 = acc[t][1] + b1;
        const float v02 = acc[t][2] + b0,     v03 = acc[t][3] + b1;
        const float v10 = acc[8 + t][0] + b0, v11 = acc[8 + t][1] + b1;
        const float v12 = acc[8 + t][2] + b0, v13 = acc[8 + t][3] + b1;
        const size_t r = rowBase + mw * 32 + g;
        *(uint32_t*)(g_emb + r * DIM + col)        = h2pack(v00, v01);
        *(uint32_t*)(g_emb + (r + 8) * DIM + col)  = h2pack(v02, v03);
        *(uint32_t*)(g_emb + (r + 16) * DIM + col) = h2pack(v10, v11);
        *(uint32_t*)(g_emb + (r + 24) * DIM + col) = h2pack(v12, v13);
        nrm[0] = fmaf(v00, v00, fmaf(v01, v01, nrm[0]));
        nrm[1] = fmaf(v02, v02, fmaf(v03, v03, nrm[1]));
        nrm[2] = fmaf(v10, v10, fmaf(v11, v11, nrm[2]));
        nrm[3] = fmaf(v12, v12, fmaf(v13, v13, nrm[3]));
    }
#pragma unroll
    for (int i = 0; i < 4; i++) {
        nrm[i] += __shfl_xor_sync(0xffffffffu, nrm[i], 1);
        nrm[i] += __shfl_xor_sync(0xffffffffu, nrm[i], 2);
    }
    if (tig == 0) {
        const size_t r = rowBase + mw * 32 + g;
        g_nrm8[r * 8 + nslot]        = nrm[0];
        g_nrm8[(r + 8) * 8 + nslot]  = nrm[1];
        g_nrm8[(r + 16) * 8 + nslot] = nrm[2];
        g_nrm8[(r + 24) * 8 + nslot] = nrm[3];
    }
}

// =====================================================================
// Kernel 4: NCA GEMM + half2-exp + permuted one-hot class MMA epilogue
// =====================================================================
__global__ void __launch_bounds__(256, 2)
nca_mma_kernel(const int* __restrict__ cy)
{
    extern __shared__ char sm[];
    __shared__ float s_cn[128];
    __shared__ int   s_cy[128];
    __shared__ float s_xn[128];
    __shared__ __align__(16) __half s_oh[16 * 136];
    const uint32_t sb = smem_u32(sm);
    const int tid = threadIdx.x, wid = tid >> 5, lane = tid & 31;
    const int mw = wid >> 1, nw = wid & 1;
    const int xBase = blockIdx.x * 128;
    const int cBase = blockIdx.y * 128;

    if (tid < 128) {
        const int j = cBase + tid;
        const float* p = g_nrm8 + (size_t)j * 8;
        const float s = ((p[0] + p[1]) + (p[2] + p[3])) + ((p[4] + p[5]) + (p[6] + p[7]));
        s_cn[tid] = (j < NC) ? s : 1e30f;
        s_cy[tid] = cy[min(j, NC - 1)];
    } else {
        const int r = NCPAD + xBase + (tid - 128);
        const float* p = g_nrm8 + (size_t)r * 8;
        s_xn[tid - 128] = ((p[0] + p[1]) + (p[2] + p[3])) + ((p[4] + p[5]) + (p[6] + p[7]));
    }

    const char* gA = (const char*)(g_emb + (size_t)(NCPAD + xBase) * DIM);
    const char* gB = (const char*)(g_emb + (size_t)cBase * DIM);

    float acc[16][4];
#pragma unroll
    for (int t = 0; t < 16; t++)
#pragma unroll
        for (int u = 0; u < 4; u++) acc[t][u] = 0.f;

    gemm_main<0>(sb, gA, gB, DIM * 2, 8, acc, mw, nw, wid, lane, tid);

    __syncthreads();   // ring buffers no longer read; reuse as P tile

    // one-hot with the SAME candidate permutation as the P store:
    if (tid < 128) {
        const int half = tid >> 6, nu = tid & 63;
        const int tg = nu >> 4, tt = (nu >> 1) & 7, uu = nu & 1;
        const int y = s_cy[half * 64 + tg * 2 + tt * 8 + uu];
#pragma unroll
        for (int c = 0; c < 16; c++)
            s_oh[c * 136 + tid] = (y == c) ? __float2half(1.f) : __float2half(0.f);
    }

    // scores -> e = exp(-d) in half2 (scores <= 0, no max needed)
    const int g = lane >> 2, tig = lane & 3;
    const uint32_t nl2e = h2pack(-1.4426950408889634f, -1.4426950408889634f);
    float xnr[4];
#pragma unroll
    for (int i = 0; i < 4; i++) xnr[i] = s_xn[mw * 32 + 8 * i + g];
#pragma unroll
    for (int r = 0; r < 4; r++) {
        const float xn = xnr[r];
        const int tb = (r >> 1) * 8;
        const int ub = (r & 1) * 2;
        uint32_t pout[8];
#pragma unroll
        for (int t = 0; t < 8; t++) {
            const int colb = nw * 64 + t * 8 + tig * 2;
            const float sq0 = fmaxf(xn + s_cn[colb]     - 2.f * acc[tb + t][ub],     1e-12f);
            const float sq1 = fmaxf(xn + s_cn[colb + 1] - 2.f * acc[tb + t][ub + 1], 1e-12f);
            float d0, d1;
            asm("sqrt.approx.f32 %0, %1;" : "=f"(d0) : "f"(sq0));
            asm("sqrt.approx.f32 %0, %1;" : "=f"(d1) : "f"(sq1));
            pout[t] = ex2_f16x2(mul_f16x2(cvt_f16x2(d0, d1), nl2e));
        }
        char* dst = sm + (mw * 32 + r * 8 + g) * PSTR + nw * 128 + tig * 32;
        *(uint4*)dst        = make_uint4(pout[0], pout[1], pout[2], pout[3]);
        *(uint4*)(dst + 16) = make_uint4(pout[4], pout[5], pout[6], pout[7]);
    }
    __syncthreads();

    // class GEMM: D[128 rows x 16 classes] = P(128x128) @ onehot^T, fp32 accum
    float d0[4] = {0.f, 0.f, 0.f, 0.f};
    float d1[4] = {0.f, 0.f, 0.f, 0.f};
    const uint32_t arow = sb + (uint32_t)(wid * 16 + (lane & 15)) * PSTR
                        + ((uint32_t)(lane >> 4)) * 16;
    const uint32_t ohb  = smem_u32(s_oh) + (uint32_t)(lane & 7) * PSTR
                        + ((uint32_t)((lane >> 3) & 1)) * 16;
#pragma unroll
    for (int ks = 0; ks < 8; ks++) {
        uint32_t a4[4];
        ldsm4(a4[0], a4[1], a4[2], a4[3], arow + ks * 32);
        uint32_t b0[2], b1[2];
        ldsm2(b0[0], b0[1], ohb + ks * 32);
        ldsm2(b1[0], b1[1], ohb + 8 * PSTR + ks * 32);
        mma16816(d0, a4, b0);
        mma16816(d1, a4, b1);
    }
    {
        const int tg = lane & 3;
        float* P0 = g_part + ((size_t)(xBase + wid * 16 + g) * NSPLIT + blockIdx.y) * D_OUT;
        float* P1 = g_part + ((size_t)(xBase + wid * 16 + 8 + g) * NSPLIT + blockIdx.y) * D_OUT;
        P0[tg * 2]     = d0[0];
        P0[tg * 2 + 1] = d0[1];
        P1[tg * 2]     = d0[2];
        P1[tg * 2 + 1] = d0[3];
        if (tg == 0) {
            P0[8] = d1[0]; P0[9] = d1[1];
            P1[8] = d1[2]; P1[9] = d1[3];
        }
    }
}

// =====================================================================
// Kernel 5: reduce partials -> log-probs (warp per x row, deterministic)
// =====================================================================
__global__ void __launch_bounds__(256)
finalize_kernel(float* __restrict__ out)
{
    const int w = (blockIdx.x * 256 + threadIdx.x) >> 5;
    const int lane = threadIdx.x & 31;
    if (w >= NX) return;
    const float* P = g_part + (size_t)w * NSPLIT * D_OUT;
    float n[D_OUT];
#pragma unroll
    for (int c = 0; c < D_OUT; c++) n[c] = 0.f;
    for (int s = lane; s < NSPLIT; s += 32) {
        const float* q = P + s * D_OUT;
#pragma unroll
        for (int c = 0; c < D_OUT; c++) n[c] += q[c];
    }
#pragma unroll
    for (int o = 16; o; o >>= 1)
#pragma unroll
        for (int c = 0; c < D_OUT; c++) n[c] += __shfl_xor_sync(0xffffffffu, n[c], o);
    if (lane == 0) {
        float l = 0.f;
#pragma unroll
        for (int c = 0; c < D_OUT; c++) l += n[c];
        const float inv = 1.0f / l;
#pragma unroll
        for (int c = 0; c < D_OUT; c++)
            out[w * D_OUT + c] = logf(n[c] * inv + 1e-7f);
    }
}

// =====================================================================
extern "C" void kernel_launch(void* const* d_in, const int* in_sizes, int n_in,
                              void* d_out, int out_size)
{
    const float* x     = (const float*)d_in[0];
    const float* cx    = (const float*)d_in[1];
    const int*   cy    = (const int*)d_in[2];
    const float* freq  = (const float*)d_in[3];
    const float* plr_w = (const float*)d_in[4];
    const float* plr_b = (const float*)d_in[5];
    const float* enc_w = (const float*)d_in[6];
    const float* enc_b = (const float*)d_in[7];
    float* out = (float*)d_out;

    cudaFuncSetAttribute(enc_mma_kernel, cudaFuncAttributeMaxDynamicSharedMemorySize, DYNSMEM);
    cudaFuncSetAttribute(nca_mma_kernel, cudaFuncAttributeMaxDynamicSharedMemorySize, DYNSMEM);

    featgen_kernel<<<NROWS / 128, 256>>>(cx, x, freq, plr_w, plr_b);
    wprep_kernel<<<(DIM * KF + 255) / 256, 256>>>(enc_w);
    enc_mma_kernel<<<dim3(DIM / 128, NROWS / 128), 256, DYNSMEM>>>(enc_b);
    nca_mma_kernel<<<dim3(NX / 128, NCPAD / 128), 256, DYNSMEM>>>(cy);
    finalize_kernel<<<(NX * 32) / 256, 256>>>(out);
}